// round 2
// baseline (speedup 1.0000x reference)
#include <cuda_runtime.h>
#include <math.h>

#define EN 300000
#define NN 50000
#define GN 1024
#define H  256
#define NCONV 4

// ---------------- scratch (device globals; no allocation allowed) ----------
static __device__ float g_bond[(size_t)EN * H];   // 307 MB: bond_attr [E,H]
static __device__ float g_h[NN * H];              // node features
static __device__ float g_aggr[NN * H];           // segment-sum accumulator
static __device__ float g_tmp[NN * H];            // GIN hidden1
static __device__ float g_temb[GN];               // per-graph time scalar
static __device__ float g_invstd[GN];             // per-graph 1/std
static __device__ float g_comb[H + 1];            // temb_W@dense1_W (+bias)
static __device__ float g_einv[EN];               // per-edge 1/std

// ---------------- temb combine: comb = temb_W @ dense1_W -------------------
__global__ void comb_kernel(const float* __restrict__ tW, const float* __restrict__ tb,
                            const float* __restrict__ d1W, const float* __restrict__ d1b)
{
    int i = threadIdx.x;
    float s = 0.f;
    for (int k = 0; k < H; k++) s += tW[i * H + k] * d1W[k];
    g_comb[i] = s;
    if (i == 0) {
        float c = 0.f;
        for (int k = 0; k < H; k++) c += tb[k] * d1W[k];
        g_comb[H] = c + d1b[0];
    }
}

// ---------------- per-graph time embedding + 1/std -------------------------
__global__ void temb_kernel(const float* __restrict__ t, const float* __restrict__ fw)
{
    __shared__ float red[128];
    int g = blockIdx.x, i = threadIdx.x;
    float tt = t[g];
    float xp = tt * fw[i] * 6.283185307179586f;
    red[i] = sinf(xp) * g_comb[i] + cosf(xp) * g_comb[128 + i];
    __syncthreads();
    for (int s = 64; s > 0; s >>= 1) {
        if (i < s) red[i] += red[i + s];
        __syncthreads();
    }
    if (i == 0) {
        g_temb[g] = red[0] + g_comb[H];
        const float LS = 3.2188758248682006f;   // ln(25)
        float var = (expf(2.f * tt * LS) - 1.f) / (2.f * LS);
        g_invstd[g] = rsqrtf(var);
    }
}

// ---------------- h0 = atom_emb[node_type] ---------------------------------
__global__ void __launch_bounds__(256) init_h(const int* __restrict__ nt,
                                              const float* __restrict__ atom_emb)
{
    int idx = blockIdx.x * blockDim.x + threadIdx.x;
    if (idx >= NN * 64) return;
    int n = idx >> 6, q = idx & 63;
    ((float4*)g_h)[idx] = ((const float4*)atom_emb)[nt[n] * 64 + q];
}

// ---------------- edge features: bond_attr & per-edge 1/std ----------------
// 32 edges per block, 256 threads. h1 (rank-1 first layer) in smem, then
// 256x256 second layer with broadcast smem reads.
__global__ void __launch_bounds__(256)
edge_feat(const float* __restrict__ elen, const int* __restrict__ src,
          const int* __restrict__ batch, const int* __restrict__ etype,
          const float* __restrict__ W1, const float* __restrict__ b1,
          const float* __restrict__ W2, const float* __restrict__ b2,
          const float* __restrict__ bond_emb)
{
    __shared__ float h1s[H][32];
    __shared__ float xs[32];
    __shared__ float tembs[32];
    __shared__ int   ets[32];
    int tid = threadIdx.x;
    int e0 = blockIdx.x * 32;

    if (tid < 32) {
        int e = e0 + tid;
        xs[tid] = elen[e];
        int g = batch[src[e]];
        tembs[tid] = g_temb[g];
        g_einv[e] = g_invstd[g];
        ets[tid] = etype[e];
    }
    __syncthreads();

    // phase 1: h1[j][e] = relu(x_e * W1[j] + b1[j]); warp shares j (broadcast W1)
    {
        int el = tid & 31;
        int jb = (tid >> 5) * 32;
        float x = xs[el];
#pragma unroll 8
        for (int jj = 0; jj < 32; jj++) {
            int j = jb + jj;
            h1s[j][el] = fmaxf(x * W1[j] + b1[j], 0.f);
        }
    }
    __syncthreads();

    // phase 2: out[e][k] = (h1[e]·W2[:,k] + b2[k] + temb) * bond_emb
    int k = tid;
    float acc[32];
#pragma unroll
    for (int e = 0; e < 32; e++) acc[e] = 0.f;
    for (int j = 0; j < H; j++) {
        float w = W2[j * H + k];
        const float4* hv = (const float4*)&h1s[j][0];
#pragma unroll
        for (int q = 0; q < 8; q++) {
            float4 v = hv[q];
            acc[q * 4 + 0] += v.x * w;
            acc[q * 4 + 1] += v.y * w;
            acc[q * 4 + 2] += v.z * w;
            acc[q * 4 + 3] += v.w * w;
        }
    }
    float bb = b2[k];
#pragma unroll
    for (int e = 0; e < 32; e++) {
        float be = bond_emb[ets[e] * H + k];
        g_bond[(size_t)(e0 + e) * H + k] = (acc[e] + bb + tembs[e]) * be;
    }
}

// ---------------- zero aggr -------------------------------------------------
__global__ void __launch_bounds__(256) zero_aggr()
{
    int idx = blockIdx.x * blockDim.x + threadIdx.x;
    if (idx >= NN * 64) return;
    ((float4*)g_aggr)[idx] = make_float4(0.f, 0.f, 0.f, 0.f);
}

// ---------------- scatter: aggr[dst] += relu(h[src] + bond) -----------------
__global__ void __launch_bounds__(256)
scatter(const int* __restrict__ src, const int* __restrict__ dst)
{
    int idx = blockIdx.x * blockDim.x + threadIdx.x;
    if (idx >= EN * 64) return;
    int e = idx >> 6, q = idx & 63;
    int s = src[e], d = dst[e];
    float4 hv = ((const float4*)g_h)[s * 64 + q];
    float4 bv = ((const float4*)g_bond)[(size_t)e * 64 + q];
    float4 m;
    m.x = fmaxf(hv.x + bv.x, 0.f);
    m.y = fmaxf(hv.y + bv.y, 0.f);
    m.z = fmaxf(hv.z + bv.z, 0.f);
    m.w = fmaxf(hv.w + bv.w, 0.f);
    float* ap = &g_aggr[d * H + q * 4];
    atomicAdd(ap + 0, m.x);
    atomicAdd(ap + 1, m.y);
    atomicAdd(ap + 2, m.z);
    atomicAdd(ap + 3, m.w);
}

// ---------------- 64x64x16 tiled fp32 GEMM ---------------------------------
// MODE 0: C(g_tmp) = relu((g_h + g_aggr) @ W + b)
// MODE 1: g_h = maybe_relu(g_tmp @ W + b) + g_h
template <int MODE>
__global__ void __launch_bounds__(256)
gemm64(const float* __restrict__ W, const float* __restrict__ bias, int reluOut)
{
    const float* A1 = (MODE == 0) ? g_h : g_tmp;
    const float* A2 = (MODE == 0) ? g_aggr : nullptr;
    const float* R  = (MODE == 0) ? nullptr : g_h;
    float* C        = (MODE == 0) ? g_tmp : g_h;
    const int M = NN;

    __shared__ float As[16][64];
    __shared__ float Bs[16][64];
    int tid = threadIdx.x;
    int m0 = blockIdx.y * 64, n0 = blockIdx.x * 64;
    int tx = tid & 15, ty = tid >> 4;
    int lm = tid >> 2;
    int lk = (tid & 3) * 4;
    int bk = tid >> 4;
    int bn = (tid & 15) * 4;
    float acc[4][4] = {};

    for (int k0 = 0; k0 < H; k0 += 16) {
        int row = m0 + lm;
        float4 a = make_float4(0.f, 0.f, 0.f, 0.f);
        if (row < M) {
            a = *(const float4*)&A1[row * H + k0 + lk];
            if (MODE == 0) {
                float4 a2 = *(const float4*)&A2[row * H + k0 + lk];
                a.x += a2.x; a.y += a2.y; a.z += a2.z; a.w += a2.w;
            }
        }
        As[lk + 0][lm] = a.x;
        As[lk + 1][lm] = a.y;
        As[lk + 2][lm] = a.z;
        As[lk + 3][lm] = a.w;
        *(float4*)&Bs[bk][bn] = *(const float4*)&W[(k0 + bk) * H + n0 + bn];
        __syncthreads();
#pragma unroll
        for (int kk = 0; kk < 16; kk++) {
            float4 av = *(const float4*)&As[kk][ty * 4];
            float4 bv = *(const float4*)&Bs[kk][tx * 4];
            float aa[4] = {av.x, av.y, av.z, av.w};
            float bb[4] = {bv.x, bv.y, bv.z, bv.w};
#pragma unroll
            for (int i = 0; i < 4; i++)
#pragma unroll
                for (int j = 0; j < 4; j++) acc[i][j] += aa[i] * bb[j];
        }
        __syncthreads();
    }

#pragma unroll
    for (int i = 0; i < 4; i++) {
        int row = m0 + ty * 4 + i;
        if (row >= M) break;
#pragma unroll
        for (int j = 0; j < 4; j++) {
            int col = n0 + tx * 4 + j;
            float v = acc[i][j] + bias[col];
            if (reluOut) v = fmaxf(v, 0.f);
            if (MODE == 1) v += R[row * H + col];
            C[row * H + col] = v;
        }
    }
}

// ---------------- fused output MLP: 16 edges/block --------------------------
__global__ void __launch_bounds__(256)
out_mlp(const int* __restrict__ src, const int* __restrict__ dst,
        const float* __restrict__ W1, const float* __restrict__ b1,
        const float* __restrict__ W2, const float* __restrict__ b2,
        const float* __restrict__ W3, const float* __restrict__ b3,
        float* __restrict__ out)
{
    __shared__ float feats[512][16];   // 32 KB
    __shared__ float h1s[H * 16];      // 16 KB  (total = 48 KB exactly)
    int tid = threadIdx.x;
    int e0 = blockIdx.x * 16;

    // phase 0: feat = [h_src*h_dst (256), bond (256)]
    {
        int el = tid & 15;
        int jl = tid >> 4;
        int e = e0 + el;
        const float* hs = &g_h[src[e] * H];
        const float* hd = &g_h[dst[e] * H];
#pragma unroll
        for (int i = 0; i < 16; i++) {
            int j = jl + 16 * i;
            feats[j][el] = hs[j] * hd[j];
        }
        const float* bp = &g_bond[(size_t)e * H];
#pragma unroll
        for (int i = 0; i < 16; i++) {
            int j = jl + 16 * i;
            feats[256 + j][el] = bp[j];
        }
    }
    __syncthreads();

    // phase 1: h1 = relu(feat @ W1 + b1)   [512 -> 256]
    {
        int k = tid;
        float acc[16];
#pragma unroll
        for (int e = 0; e < 16; e++) acc[e] = 0.f;
        for (int j = 0; j < 512; j++) {
            float w = W1[j * H + k];
            const float4* fv = (const float4*)&feats[j][0];
#pragma unroll
            for (int q = 0; q < 4; q++) {
                float4 v = fv[q];
                acc[q * 4 + 0] += v.x * w;
                acc[q * 4 + 1] += v.y * w;
                acc[q * 4 + 2] += v.z * w;
                acc[q * 4 + 3] += v.w * w;
            }
        }
        float bb = b1[k];
#pragma unroll
        for (int e = 0; e < 16; e++) h1s[k * 16 + e] = fmaxf(acc[e] + bb, 0.f);
    }
    __syncthreads();

    // phase 2: h2 = relu(h1 @ W2 + b2)   [256 -> 128]; h2 aliases feats
    float* h2s = &feats[0][0];
    if (tid < 128) {
        float acc2[16];
#pragma unroll
        for (int e = 0; e < 16; e++) acc2[e] = 0.f;
        for (int j = 0; j < H; j++) {
            float w = W2[j * 128 + tid];
            const float4* hv = (const float4*)&h1s[j * 16];
#pragma unroll
            for (int q = 0; q < 4; q++) {
                float4 v = hv[q];
                acc2[q * 4 + 0] += v.x * w;
                acc2[q * 4 + 1] += v.y * w;
                acc2[q * 4 + 2] += v.z * w;
                acc2[q * 4 + 3] += v.w * w;
            }
        }
        float bb = b2[tid];
#pragma unroll
        for (int e = 0; e < 16; e++) h2s[tid * 16 + e] = fmaxf(acc2[e] + bb, 0.f);
    }
    __syncthreads();

    // phase 3: score = h2 · W3 + b3; out = score * (1/std)
    if (tid < 16) {
        int e = e0 + tid;
        float s = 0.f;
        for (int j = 0; j < 128; j++) s += h2s[j * 16 + tid] * W3[j];
        out[e] = (s + b3[0]) * g_einv[e];
    }
}

// ---------------- launch ----------------------------------------------------
extern "C" void kernel_launch(void* const* d_in, const int* in_sizes, int n_in,
                              void* d_out, int out_size)
{
    const int*   node_type = (const int*)d_in[0];
    const int*   edge_type = (const int*)d_in[1];
    const int*   edge_index = (const int*)d_in[2];
    const int*   batch = (const int*)d_in[3];
    const float* elen = (const float*)d_in[4];
    const float* t = (const float*)d_in[5];
    const float* atom_emb = (const float*)d_in[6];
    const float* bond_emb = (const float*)d_in[7];
    const float* in_W1 = (const float*)d_in[8];
    const float* in_b1 = (const float*)d_in[9];
    const float* in_W2 = (const float*)d_in[10];
    const float* in_b2 = (const float*)d_in[11];
    const float* fourier_W = (const float*)d_in[12];
    const float* temb_W = (const float*)d_in[13];
    const float* temb_b = (const float*)d_in[14];
    const float* d1W = (const float*)d_in[15];
    const float* d1b = (const float*)d_in[16];
    const float* gin_W1 = (const float*)d_in[17];
    const float* gin_b1 = (const float*)d_in[18];
    const float* gin_W2 = (const float*)d_in[19];
    const float* gin_b2 = (const float*)d_in[20];
    const float* out_W1 = (const float*)d_in[21];
    const float* out_b1 = (const float*)d_in[22];
    const float* out_W2 = (const float*)d_in[23];
    const float* out_b2 = (const float*)d_in[24];
    const float* out_W3 = (const float*)d_in[25];
    const float* out_b3 = (const float*)d_in[26];
    const int* src = edge_index;
    const int* dst = edge_index + EN;
    float* out = (float*)d_out;

    init_h<<<(NN * 64 + 255) / 256, 256>>>(node_type, atom_emb);
    comb_kernel<<<1, 256>>>(temb_W, temb_b, d1W, d1b);
    temb_kernel<<<GN, 128>>>(t, fourier_W);
    edge_feat<<<EN / 32, 256>>>(elen, src, batch, edge_type,
                                in_W1, in_b1, in_W2, in_b2, bond_emb);

    for (int c = 0; c < NCONV; c++) {
        zero_aggr<<<(NN * 64 + 255) / 256, 256>>>();
        scatter<<<(EN * 64 + 255) / 256, 256>>>(src, dst);
        gemm64<0><<<dim3(4, (NN + 63) / 64), 256>>>(gin_W1 + c * H * H, gin_b1 + c * H, 1);
        gemm64<1><<<dim3(4, (NN + 63) / 64), 256>>>(gin_W2 + c * H * H, gin_b2 + c * H,
                                                    (c < NCONV - 1) ? 1 : 0);
    }

    out_mlp<<<EN / 16, 256>>>(src, dst, out_W1, out_b1, out_W2, out_b2,
                              out_W3, out_b3, out);
}

// round 4
// speedup vs baseline: 2.0334x; 2.0334x over previous
#include <cuda_runtime.h>
#include <math.h>
#include <stdint.h>

#define EN 300000
#define NN 50000
#define GN 1024
#define H  256
#define NCONV 4
#define PADW 132   // padded smem row (floats) -> conflict-free frag reads

// ---------------- scratch (device globals) ---------------------------------
static __device__ float g_bond[(size_t)EN * H];   // bond_attr [E,H]
static __device__ float g_h1[(size_t)EN * H];     // out-MLP hidden1 [E,H]
static __device__ float g_h[NN * H];
static __device__ float g_aggr[NN * H];
static __device__ float g_tmp[NN * H];
static __device__ float g_temb[GN];
static __device__ float g_invstd[GN];
static __device__ float g_comb[H + 1];
static __device__ float g_einv[EN];

// ---------------- helpers ---------------------------------------------------
__device__ __forceinline__ float totf(float x) {
    uint32_t u; asm("cvt.rna.tf32.f32 %0, %1;" : "=r"(u) : "f"(x));
    return __uint_as_float(u);
}

// store 8 A-values (already float4 pairs) column-major into As[k][m]
__device__ __forceinline__ void store_a8(float* As, int kq, int r,
                                         float4 v0, float4 v1) {
    As[(kq + 0) * PADW + r] = totf(v0.x);
    As[(kq + 1) * PADW + r] = totf(v0.y);
    As[(kq + 2) * PADW + r] = totf(v0.z);
    As[(kq + 3) * PADW + r] = totf(v0.w);
    As[(kq + 4) * PADW + r] = totf(v1.x);
    As[(kq + 5) * PADW + r] = totf(v1.y);
    As[(kq + 6) * PADW + r] = totf(v1.z);
    As[(kq + 7) * PADW + r] = totf(v1.w);
}

// load 16x128 weight tile (row-major W, leading dim ldw) into Bs[k][n]
__device__ __forceinline__ void load_w_tile(float* Bs, const float* __restrict__ W,
                                            int ldw, int k0, int n0, int tid) {
    int kr = tid >> 4;            // 0..15
    int nq = (tid & 15) * 8;      // 0..120
    const float* p = &W[(size_t)(k0 + kr) * ldw + n0 + nq];
    float4 v0 = *(const float4*)p;
    float4 v1 = *(const float4*)(p + 4);
    float* d = &Bs[kr * PADW + nq];
    d[0] = totf(v0.x); d[1] = totf(v0.y); d[2] = totf(v0.z); d[3] = totf(v0.w);
    d[4] = totf(v1.x); d[5] = totf(v1.y); d[6] = totf(v1.z); d[7] = totf(v1.w);
}

// one k8 step: warp (wy,wx) computes 32x64 with 16 mma m16n8k8
__device__ __forceinline__ void mma_k8(float acc[2][8][4],
                                       const float* As, const float* Bs,
                                       int kk, int wy, int wx, int lane) {
    int g = lane >> 2, t4 = lane & 3;
    float a[2][4];
#pragma unroll
    for (int mt = 0; mt < 2; mt++) {
        int rm = wy * 32 + mt * 16 + g;
        a[mt][0] = As[(kk + t4) * PADW + rm];
        a[mt][1] = As[(kk + t4) * PADW + rm + 8];
        a[mt][2] = As[(kk + t4 + 4) * PADW + rm];
        a[mt][3] = As[(kk + t4 + 4) * PADW + rm + 8];
    }
#pragma unroll
    for (int nt = 0; nt < 8; nt++) {
        int cn = wx * 64 + nt * 8 + g;
        float b0 = Bs[(kk + t4) * PADW + cn];
        float b1 = Bs[(kk + t4 + 4) * PADW + cn];
#pragma unroll
        for (int mt = 0; mt < 2; mt++) {
            asm volatile(
                "mma.sync.aligned.m16n8k8.row.col.f32.tf32.tf32.f32 "
                "{%0,%1,%2,%3}, {%4,%5,%6,%7}, {%8,%9}, {%0,%1,%2,%3};\n"
                : "+f"(acc[mt][nt][0]), "+f"(acc[mt][nt][1]),
                  "+f"(acc[mt][nt][2]), "+f"(acc[mt][nt][3])
                : "r"(__float_as_uint(a[mt][0])), "r"(__float_as_uint(a[mt][1])),
                  "r"(__float_as_uint(a[mt][2])), "r"(__float_as_uint(a[mt][3])),
                  "r"(__float_as_uint(b0)), "r"(__float_as_uint(b1)));
        }
    }
}

// ---------------- small setup kernels ---------------------------------------
__global__ void comb_kernel(const float* __restrict__ tW, const float* __restrict__ tb,
                            const float* __restrict__ d1W, const float* __restrict__ d1b) {
    int i = threadIdx.x;
    float s = 0.f;
    for (int k = 0; k < H; k++) s += tW[i * H + k] * d1W[k];
    g_comb[i] = s;
    if (i == 0) {
        float c = 0.f;
        for (int k = 0; k < H; k++) c += tb[k] * d1W[k];
        g_comb[H] = c + d1b[0];
    }
}

__global__ void temb_kernel(const float* __restrict__ t, const float* __restrict__ fw) {
    __shared__ float red[128];
    int g = blockIdx.x, i = threadIdx.x;
    float tt = t[g];
    float xp = tt * fw[i] * 6.283185307179586f;
    red[i] = sinf(xp) * g_comb[i] + cosf(xp) * g_comb[128 + i];
    __syncthreads();
    for (int s = 64; s > 0; s >>= 1) {
        if (i < s) red[i] += red[i + s];
        __syncthreads();
    }
    if (i == 0) {
        g_temb[g] = red[0] + g_comb[H];
        const float LS = 3.2188758248682006f;   // ln(25)
        float var = (expf(2.f * tt * LS) - 1.f) / (2.f * LS);
        g_invstd[g] = rsqrtf(var);
    }
}

__global__ void __launch_bounds__(256) init_h(const int* __restrict__ nt,
                                              const float* __restrict__ atom_emb) {
    int idx = blockIdx.x * blockDim.x + threadIdx.x;
    if (idx >= NN * 64) return;
    int n = idx >> 6, q = idx & 63;
    ((float4*)g_h)[idx] = ((const float4*)atom_emb)[nt[n] * 64 + q];
}

__global__ void __launch_bounds__(256) zero_aggr() {
    int idx = blockIdx.x * blockDim.x + threadIdx.x;
    if (idx >= NN * 64) return;
    ((float4*)g_aggr)[idx] = make_float4(0.f, 0.f, 0.f, 0.f);
}

__global__ void __launch_bounds__(256)
scatter(const int* __restrict__ src, const int* __restrict__ dst) {
    int idx = blockIdx.x * blockDim.x + threadIdx.x;
    if (idx >= EN * 64) return;
    int e = idx >> 6, q = idx & 63;
    int s = src[e], d = dst[e];
    float4 hv = ((const float4*)g_h)[s * 64 + q];
    float4 bv = ((const float4*)g_bond)[(size_t)e * 64 + q];
    float* ap = &g_aggr[d * H + q * 4];
    atomicAdd(ap + 0, fmaxf(hv.x + bv.x, 0.f));
    atomicAdd(ap + 1, fmaxf(hv.y + bv.y, 0.f));
    atomicAdd(ap + 2, fmaxf(hv.z + bv.z, 0.f));
    atomicAdd(ap + 3, fmaxf(hv.w + bv.w, 0.f));
}

// ---------------- edge_bond: g_bond = (MLP(elen)+temb)*bond_emb (tf32 mma) --
__global__ void __launch_bounds__(256)
edge_bond(const float* __restrict__ elen, const int* __restrict__ src,
          const int* __restrict__ batch, const int* __restrict__ etype,
          const float* __restrict__ W1, const float* __restrict__ b1,
          const float* __restrict__ W2, const float* __restrict__ b2,
          const float* __restrict__ bond_emb) {
    __shared__ float As[16 * PADW], Bs[16 * PADW];
    __shared__ float xS[128], tS[128];
    __shared__ int eS[128];
    __shared__ float w1S[H], b1S[H];
    int tid = threadIdx.x, lane = tid & 31, warp = tid >> 5;
    int wy = warp >> 1, wx = warp & 1;
    int m0 = blockIdx.y * 128, n0 = blockIdx.x * 128;

    if (tid < 128) {
        int e = m0 + tid;
        float x = 0.f, tb = 0.f; int et = 0;
        if (e < EN) {
            x = elen[e];
            int gph = batch[src[e]];
            tb = g_temb[gph];
            if (n0 == 0) g_einv[e] = g_invstd[gph];
            et = etype[e];
        }
        xS[tid] = x; tS[tid] = tb; eS[tid] = et;
    }
    w1S[tid] = W1[tid];
    b1S[tid] = b1[tid];
    __syncthreads();

    float acc[2][8][4] = {};
    int r = tid >> 1, kq = (tid & 1) * 8;
    float x = xS[r];
    for (int k0 = 0; k0 < H; k0 += 16) {
#pragma unroll
        for (int i = 0; i < 8; i++) {
            int j = k0 + kq + i;
            As[(kq + i) * PADW + r] = totf(fmaxf(fmaf(x, w1S[j], b1S[j]), 0.f));
        }
        load_w_tile(Bs, W2, H, k0, n0, tid);
        __syncthreads();
        mma_k8(acc, As, Bs, 0, wy, wx, lane);
        mma_k8(acc, As, Bs, 8, wy, wx, lane);
        __syncthreads();
    }

    int g = lane >> 2, t4 = lane & 3;
#pragma unroll
    for (int mt = 0; mt < 2; mt++)
#pragma unroll
        for (int half = 0; half < 2; half++) {
            int rl = wy * 32 + mt * 16 + g + half * 8;
            int row = m0 + rl;
            if (row >= EN) continue;
            float tb = tS[rl];
            const float* bep = &bond_emb[eS[rl] * H];
#pragma unroll
            for (int nt = 0; nt < 8; nt++) {
                int col = n0 + wx * 64 + nt * 8 + 2 * t4;
                float v0 = (acc[mt][nt][half * 2 + 0] + b2[col] + tb) * bep[col];
                float v1 = (acc[mt][nt][half * 2 + 1] + b2[col + 1] + tb) * bep[col + 1];
                *(float2*)&g_bond[(size_t)row * H + col] = make_float2(v0, v1);
            }
        }
}

// ---------------- GIN GEMMs (tf32 mma) --------------------------------------
// MODE 0: g_tmp = relu((g_h+g_aggr)@W + b)
// MODE 1: g_h   = maybe_relu(g_tmp@W + b) + g_h
template <int MODE>
__global__ void __launch_bounds__(256)
gin_mma(const float* __restrict__ W, const float* __restrict__ bias, int reluOut) {
    __shared__ float As[16 * PADW], Bs[16 * PADW];
    int tid = threadIdx.x, lane = tid & 31, warp = tid >> 5;
    int wy = warp >> 1, wx = warp & 1;
    int m0 = blockIdx.y * 128, n0 = blockIdx.x * 128;
    float acc[2][8][4] = {};
    int r = tid >> 1, kq = (tid & 1) * 8;
    int arow = m0 + r;
    const float* A1 = (MODE == 0) ? g_h : g_tmp;

    for (int k0 = 0; k0 < H; k0 += 16) {
        float4 v0 = make_float4(0.f, 0.f, 0.f, 0.f), v1 = v0;
        if (arow < NN) {
            const float* p = &A1[arow * H + k0 + kq];
            v0 = *(const float4*)p; v1 = *(const float4*)(p + 4);
            if (MODE == 0) {
                const float* q = &g_aggr[arow * H + k0 + kq];
                float4 w0 = *(const float4*)q, w1 = *(const float4*)(q + 4);
                v0.x += w0.x; v0.y += w0.y; v0.z += w0.z; v0.w += w0.w;
                v1.x += w1.x; v1.y += w1.y; v1.z += w1.z; v1.w += w1.w;
            }
        }
        store_a8(As, kq, r, v0, v1);
        load_w_tile(Bs, W, H, k0, n0, tid);
        __syncthreads();
        mma_k8(acc, As, Bs, 0, wy, wx, lane);
        mma_k8(acc, As, Bs, 8, wy, wx, lane);
        __syncthreads();
    }

    int g = lane >> 2, t4 = lane & 3;
#pragma unroll
    for (int mt = 0; mt < 2; mt++)
#pragma unroll
        for (int half = 0; half < 2; half++) {
            int row = m0 + wy * 32 + mt * 16 + g + half * 8;
            if (row >= NN) continue;
#pragma unroll
            for (int nt = 0; nt < 8; nt++) {
                int col = n0 + wx * 64 + nt * 8 + 2 * t4;
                float v0 = acc[mt][nt][half * 2 + 0] + bias[col];
                float v1 = acc[mt][nt][half * 2 + 1] + bias[col + 1];
                if (reluOut) { v0 = fmaxf(v0, 0.f); v1 = fmaxf(v1, 0.f); }
                if (MODE == 0) {
                    *(float2*)&g_tmp[row * H + col] = make_float2(v0, v1);
                } else {
                    float2 rh = *(const float2*)&g_h[row * H + col];
                    *(float2*)&g_h[row * H + col] = make_float2(v0 + rh.x, v1 + rh.y);
                }
            }
        }
}

// ---------------- out layer 1: g_h1 = relu(feat@W1 + b1)  (K=512) -----------
__global__ void __launch_bounds__(256)
out1(const int* __restrict__ src, const int* __restrict__ dst,
     const float* __restrict__ W1, const float* __restrict__ b1) {
    __shared__ float As[16 * PADW], Bs[16 * PADW];
    __shared__ int srcS[128], dstS[128];
    int tid = threadIdx.x, lane = tid & 31, warp = tid >> 5;
    int wy = warp >> 1, wx = warp & 1;
    int m0 = blockIdx.y * 128, n0 = blockIdx.x * 128;

    if (tid < 128) {
        int e = m0 + tid;
        int s = 0, d = 0;
        if (e < EN) { s = src[e]; d = dst[e]; }
        srcS[tid] = s; dstS[tid] = d;
    }
    __syncthreads();

    float acc[2][8][4] = {};
    int r = tid >> 1, kq = (tid & 1) * 8;
    int e = m0 + r;
    bool valid = (e < EN);

    for (int k0 = 0; k0 < 512; k0 += 16) {
        float4 v0, v1;
        if (k0 < 256) {
            const float* hs = &g_h[srcS[r] * H + k0 + kq];
            const float* hd = &g_h[dstS[r] * H + k0 + kq];
            float4 a0 = *(const float4*)hs, a1 = *(const float4*)(hs + 4);
            float4 c0 = *(const float4*)hd, c1 = *(const float4*)(hd + 4);
            v0 = make_float4(a0.x * c0.x, a0.y * c0.y, a0.z * c0.z, a0.w * c0.w);
            v1 = make_float4(a1.x * c1.x, a1.y * c1.y, a1.z * c1.z, a1.w * c1.w);
        } else if (valid) {
            const float* bp = &g_bond[(size_t)e * H + (k0 - 256) + kq];
            v0 = *(const float4*)bp; v1 = *(const float4*)(bp + 4);
        } else {
            v0 = make_float4(0.f, 0.f, 0.f, 0.f); v1 = v0;
        }
        store_a8(As, kq, r, v0, v1);
        load_w_tile(Bs, W1, H, k0, n0, tid);
        __syncthreads();
        mma_k8(acc, As, Bs, 0, wy, wx, lane);
        mma_k8(acc, As, Bs, 8, wy, wx, lane);
        __syncthreads();
    }

    int g = lane >> 2, t4 = lane & 3;
#pragma unroll
    for (int mt = 0; mt < 2; mt++)
#pragma unroll
        for (int half = 0; half < 2; half++) {
            int row = m0 + wy * 32 + mt * 16 + g + half * 8;
            if (row >= EN) continue;
#pragma unroll
            for (int nt = 0; nt < 8; nt++) {
                int col = n0 + wx * 64 + nt * 8 + 2 * t4;
                float v0 = fmaxf(acc[mt][nt][half * 2 + 0] + b1[col], 0.f);
                float v1 = fmaxf(acc[mt][nt][half * 2 + 1] + b1[col + 1], 0.f);
                *(float2*)&g_h1[(size_t)row * H + col] = make_float2(v0, v1);
            }
        }
}

// ---------------- out layers 2+3 fused: score & scale (N=128) ---------------
__global__ void __launch_bounds__(256)
out23(const float* __restrict__ W2, const float* __restrict__ b2,
      const float* __restrict__ W3, const float* __restrict__ b3,
      float* __restrict__ out) {
    __shared__ float As[16 * PADW], Bs[16 * PADW];
    __shared__ float red[128 * 8];
    __shared__ float b2S[128], w3S[128];
    int tid = threadIdx.x, lane = tid & 31, warp = tid >> 5;
    int wy = warp >> 1, wx = warp & 1;
    int m0 = blockIdx.x * 128;

    if (tid < 128) { b2S[tid] = b2[tid]; w3S[tid] = W3[tid]; }
    __syncthreads();

    float acc[2][8][4] = {};
    int r = tid >> 1, kq = (tid & 1) * 8;
    int e = m0 + r;
    bool valid = (e < EN);

    for (int k0 = 0; k0 < H; k0 += 16) {
        float4 v0 = make_float4(0.f, 0.f, 0.f, 0.f), v1 = v0;
        if (valid) {
            const float* p = &g_h1[(size_t)e * H + k0 + kq];
            v0 = *(const float4*)p; v1 = *(const float4*)(p + 4);
        }
        store_a8(As, kq, r, v0, v1);
        load_w_tile(Bs, W2, 128, k0, 0, tid);
        __syncthreads();
        mma_k8(acc, As, Bs, 0, wy, wx, lane);
        mma_k8(acc, As, Bs, 8, wy, wx, lane);
        __syncthreads();
    }

    int g = lane >> 2, t4 = lane & 3;
#pragma unroll
    for (int mt = 0; mt < 2; mt++)
#pragma unroll
        for (int half = 0; half < 2; half++) {
            int rl = wy * 32 + mt * 16 + g + half * 8;
            float partial = 0.f;
#pragma unroll
            for (int nt = 0; nt < 8; nt++) {
                int col = wx * 64 + nt * 8 + 2 * t4;
                float h0 = fmaxf(acc[mt][nt][half * 2 + 0] + b2S[col], 0.f);
                float h1 = fmaxf(acc[mt][nt][half * 2 + 1] + b2S[col + 1], 0.f);
                partial += h0 * w3S[col] + h1 * w3S[col + 1];
            }
            red[rl * 8 + wx * 4 + t4] = partial;
        }
    __syncthreads();

    if (tid < 128) {
        int ee = m0 + tid;
        if (ee < EN) {
            float s = 0.f;
#pragma unroll
            for (int i = 0; i < 8; i++) s += red[tid * 8 + i];
            out[ee] = (s + b3[0]) * g_einv[ee];
        }
    }
}

// ---------------- launch ----------------------------------------------------
extern "C" void kernel_launch(void* const* d_in, const int* in_sizes, int n_in,
                              void* d_out, int out_size) {
    const int*   node_type = (const int*)d_in[0];
    const int*   edge_type = (const int*)d_in[1];
    const int*   edge_index = (const int*)d_in[2];
    const int*   batch = (const int*)d_in[3];
    const float* elen = (const float*)d_in[4];
    const float* t = (const float*)d_in[5];
    const float* atom_emb = (const float*)d_in[6];
    const float* bond_emb = (const float*)d_in[7];
    const float* in_W1 = (const float*)d_in[8];
    const float* in_b1 = (const float*)d_in[9];
    const float* in_W2 = (const float*)d_in[10];
    const float* in_b2 = (const float*)d_in[11];
    const float* fourier_W = (const float*)d_in[12];
    const float* temb_W = (const float*)d_in[13];
    const float* temb_b = (const float*)d_in[14];
    const float* d1W = (const float*)d_in[15];
    const float* d1b = (const float*)d_in[16];
    const float* gin_W1 = (const float*)d_in[17];
    const float* gin_b1 = (const float*)d_in[18];
    const float* gin_W2 = (const float*)d_in[19];
    const float* gin_b2 = (const float*)d_in[20];
    const float* out_W1 = (const float*)d_in[21];
    const float* out_b1 = (const float*)d_in[22];
    const float* out_W2 = (const float*)d_in[23];
    const float* out_b2 = (const float*)d_in[24];
    const float* out_W3 = (const float*)d_in[25];
    const float* out_b3 = (const float*)d_in[26];
    const int* src = edge_index;
    const int* dst = edge_index + EN;
    float* out = (float*)d_out;

    const int EB = (EN + 127) / 128;   // 2344
    const int NB = (NN + 127) / 128;   // 391

    init_h<<<(NN * 64 + 255) / 256, 256>>>(node_type, atom_emb);
    comb_kernel<<<1, 256>>>(temb_W, temb_b, d1W, d1b);
    temb_kernel<<<GN, 128>>>(t, fourier_W);
    edge_bond<<<dim3(2, EB), 256>>>(elen, src, batch, edge_type,
                                    in_W1, in_b1, in_W2, in_b2, bond_emb);

    for (int c = 0; c < NCONV; c++) {
        zero_aggr<<<(NN * 64 + 255) / 256, 256>>>();
        scatter<<<(EN * 64 + 255) / 256, 256>>>(src, dst);
        gin_mma<0><<<dim3(2, NB), 256>>>(gin_W1 + c * H * H, gin_b1 + c * H, 1);
        gin_mma<1><<<dim3(2, NB), 256>>>(gin_W2 + c * H * H, gin_b2 + c * H,
                                         (c < NCONV - 1) ? 1 : 0);
    }

    out1<<<dim3(2, EB), 256>>>(src, dst, out_W1, out_b1);
    out23<<<EB, 256>>>(out_W2, out_b2, out_W3, out_b3, out);
}

// round 5
// speedup vs baseline: 2.0445x; 1.0054x over previous
#include <cuda_runtime.h>
#include <math.h>
#include <stdint.h>

#define EN 300000
#define NN 50000
#define GN 1024
#define H  256
#define NCONV 4
#define PADW 132

// ---------------- scratch (device globals) ---------------------------------
static __device__ float g_bond[(size_t)EN * H];   // bond_attr, DST-SORTED rows
static __device__ float g_h1[(size_t)EN * H];     // out-MLP hidden1 [E,H]
static __device__ float g_h[NN * H];
static __device__ float g_aggr[NN * H];
static __device__ float g_tmp[NN * H];
static __device__ float g_temb[GN];
static __device__ float g_invstd[GN];
static __device__ float g_comb[H + 1];
static __device__ float g_einv[EN];
// sort machinery
static __device__ int g_cnt[NN];
static __device__ int g_rp[NN + 1];
static __device__ int g_woff[NN];
static __device__ int g_pos[EN];     // edge -> sorted position
static __device__ int g_srcp[EN];    // sorted position -> src node

// ---------------- helpers ---------------------------------------------------
__device__ __forceinline__ float totf(float x) {
    uint32_t u; asm("cvt.rna.tf32.f32 %0, %1;" : "=r"(u) : "f"(x));
    return __uint_as_float(u);
}

// warp computes 64x64: acc[4][8][4]; CTA = 4 warps (2x2) -> 128x128 tile
__device__ __forceinline__ void mma_k8w(float acc[4][8][4],
                                        const float* As, const float* Bs,
                                        int kk, int wy, int wx, int lane) {
    int g = lane >> 2, t4 = lane & 3;
    float a[4][4];
#pragma unroll
    for (int mt = 0; mt < 4; mt++) {
        int rm = wy * 64 + mt * 16 + g;
        a[mt][0] = As[(kk + t4) * PADW + rm];
        a[mt][1] = As[(kk + t4) * PADW + rm + 8];
        a[mt][2] = As[(kk + t4 + 4) * PADW + rm];
        a[mt][3] = As[(kk + t4 + 4) * PADW + rm + 8];
    }
#pragma unroll
    for (int nt = 0; nt < 8; nt++) {
        int cn = wx * 64 + nt * 8 + g;
        float b0 = Bs[(kk + t4) * PADW + cn];
        float b1 = Bs[(kk + t4 + 4) * PADW + cn];
#pragma unroll
        for (int mt = 0; mt < 4; mt++) {
            asm volatile(
                "mma.sync.aligned.m16n8k8.row.col.f32.tf32.tf32.f32 "
                "{%0,%1,%2,%3}, {%4,%5,%6,%7}, {%8,%9}, {%0,%1,%2,%3};\n"
                : "+f"(acc[mt][nt][0]), "+f"(acc[mt][nt][1]),
                  "+f"(acc[mt][nt][2]), "+f"(acc[mt][nt][3])
                : "r"(__float_as_uint(a[mt][0])), "r"(__float_as_uint(a[mt][1])),
                  "r"(__float_as_uint(a[mt][2])), "r"(__float_as_uint(a[mt][3])),
                  "r"(__float_as_uint(b0)), "r"(__float_as_uint(b1)));
        }
    }
}

// B tile loader: 128 threads, 16x128 from row-major W
__device__ __forceinline__ void load_w128(float* Bs, const float* __restrict__ W,
                                          int ldw, int k0, int n0, int tid) {
    int kr = tid >> 3;            // 0..15
    int nq = (tid & 7) * 16;      // 0..112
    const float* p = &W[(size_t)(k0 + kr) * ldw + n0 + nq];
    float* d = &Bs[kr * PADW + nq];
#pragma unroll
    for (int j = 0; j < 4; j++) {
        float4 v = *(const float4*)(p + j * 4);
        d[j * 4 + 0] = totf(v.x); d[j * 4 + 1] = totf(v.y);
        d[j * 4 + 2] = totf(v.z); d[j * 4 + 3] = totf(v.w);
    }
}

// store 16 A values (thread = row r) column-major
__device__ __forceinline__ void store_a16(float* As, int r, const float v[16]) {
#pragma unroll
    for (int k = 0; k < 16; k++) As[k * PADW + r] = totf(v[k]);
}

// ---------------- small setup kernels ---------------------------------------
__global__ void comb_kernel(const float* __restrict__ tW, const float* __restrict__ tb,
                            const float* __restrict__ d1W, const float* __restrict__ d1b) {
    int i = threadIdx.x;
    float s = 0.f;
    for (int k = 0; k < H; k++) s += tW[i * H + k] * d1W[k];
    g_comb[i] = s;
    if (i == 0) {
        float c = 0.f;
        for (int k = 0; k < H; k++) c += tb[k] * d1W[k];
        g_comb[H] = c + d1b[0];
    }
}

__global__ void temb_kernel(const float* __restrict__ t, const float* __restrict__ fw) {
    __shared__ float red[128];
    int g = blockIdx.x, i = threadIdx.x;
    float tt = t[g];
    float xp = tt * fw[i] * 6.283185307179586f;
    red[i] = sinf(xp) * g_comb[i] + cosf(xp) * g_comb[128 + i];
    __syncthreads();
    for (int s = 64; s > 0; s >>= 1) {
        if (i < s) red[i] += red[i + s];
        __syncthreads();
    }
    if (i == 0) {
        g_temb[g] = red[0] + g_comb[H];
        const float LS = 3.2188758248682006f;   // ln(25)
        float var = (expf(2.f * tt * LS) - 1.f) / (2.f * LS);
        g_invstd[g] = rsqrtf(var);
    }
}

__global__ void __launch_bounds__(256) init_h(const int* __restrict__ nt,
                                              const float* __restrict__ atom_emb) {
    int idx = blockIdx.x * blockDim.x + threadIdx.x;
    if (idx >= NN * 64) return;
    int n = idx >> 6, q = idx & 63;
    ((float4*)g_h)[idx] = ((const float4*)atom_emb)[nt[n] * 64 + q];
}

// ---------------- sort-by-dst construction ----------------------------------
__global__ void __launch_bounds__(256) zero_cnt() {
    int i = blockIdx.x * blockDim.x + threadIdx.x;
    if (i < NN) g_cnt[i] = 0;
}

__global__ void __launch_bounds__(256) hist(const int* __restrict__ dst) {
    int e = blockIdx.x * blockDim.x + threadIdx.x;
    if (e < EN) atomicAdd(&g_cnt[dst[e]], 1);
}

__global__ void __launch_bounds__(1024) scan_kernel() {
    __shared__ int part[1024];
    const int CH = 49;                       // 1024*49 >= NN
    int t = threadIdx.x;
    int beg = t * CH, end = min(beg + CH, NN);
    int s = 0;
    for (int i = beg; i < end; i++) s += g_cnt[i];
    part[t] = s;
    __syncthreads();
    for (int off = 1; off < 1024; off <<= 1) {
        int v = (t >= off) ? part[t - off] : 0;
        __syncthreads();
        part[t] += v;
        __syncthreads();
    }
    int run = (t == 0) ? 0 : part[t - 1];
    for (int i = beg; i < end; i++) {
        g_rp[i] = run; g_woff[i] = run; run += g_cnt[i];
    }
    if (t == 1023) g_rp[NN] = part[1023];
}

__global__ void __launch_bounds__(256) place(const int* __restrict__ src,
                                             const int* __restrict__ dst) {
    int e = blockIdx.x * blockDim.x + threadIdx.x;
    if (e >= EN) return;
    int p = atomicAdd(&g_woff[dst[e]], 1);
    g_pos[e] = p;
    g_srcp[p] = src[e];
}

// ---------------- gather: aggr[n] = sum relu(h[src]+bond) over in-edges -----
__global__ void __launch_bounds__(256) gather() {
    int warp = threadIdx.x >> 5, lane = threadIdx.x & 31;
    int n = blockIdx.x * 8 + warp;
    if (n >= NN) return;
    int q = lane * 8;
    float4 a0 = make_float4(0.f, 0.f, 0.f, 0.f), a1 = a0;
    int beg = g_rp[n], end = g_rp[n + 1];
    for (int p = beg; p < end; p++) {
        int s = g_srcp[p];
        const float4* hp = (const float4*)&g_h[s * H + q];
        const float4* bp = (const float4*)&g_bond[(size_t)p * H + q];
        float4 h0 = hp[0], h1v = hp[1], b0 = bp[0], b1v = bp[1];
        a0.x += fmaxf(h0.x + b0.x, 0.f);  a0.y += fmaxf(h0.y + b0.y, 0.f);
        a0.z += fmaxf(h0.z + b0.z, 0.f);  a0.w += fmaxf(h0.w + b0.w, 0.f);
        a1.x += fmaxf(h1v.x + b1v.x, 0.f); a1.y += fmaxf(h1v.y + b1v.y, 0.f);
        a1.z += fmaxf(h1v.z + b1v.z, 0.f); a1.w += fmaxf(h1v.w + b1v.w, 0.f);
    }
    float4* ap = (float4*)&g_aggr[n * H + q];
    ap[0] = a0; ap[1] = a1;
}

// ---------------- edge_bond (tf32 mma, 128 thr, writes sorted rows) ---------
__global__ void __launch_bounds__(128)
edge_bond(const float* __restrict__ elen, const int* __restrict__ src,
          const int* __restrict__ batch, const int* __restrict__ etype,
          const float* __restrict__ W1, const float* __restrict__ b1,
          const float* __restrict__ W2, const float* __restrict__ b2,
          const float* __restrict__ bond_emb) {
    __shared__ float As[16 * PADW], Bs[16 * PADW];
    __shared__ float xS[128], tS[128];
    __shared__ int eS[128], pS[128];
    __shared__ float w1S[H], b1S[H];
    int tid = threadIdx.x, lane = tid & 31, warp = tid >> 5;
    int wy = warp >> 1, wx = warp & 1;
    int m0 = blockIdx.y * 128, n0 = blockIdx.x * 128;

    {
        int e = m0 + tid;
        float x = 0.f, tb = 0.f; int et = 0, ps = 0;
        if (e < EN) {
            x = elen[e];
            int gph = batch[src[e]];
            tb = g_temb[gph];
            if (n0 == 0) g_einv[e] = g_invstd[gph];
            et = etype[e];
            ps = g_pos[e];
        }
        xS[tid] = x; tS[tid] = tb; eS[tid] = et; pS[tid] = ps;
        w1S[tid] = W1[tid];         w1S[tid + 128] = W1[tid + 128];
        b1S[tid] = b1[tid];         b1S[tid + 128] = b1[tid + 128];
    }
    __syncthreads();

    float acc[4][8][4] = {};
    float x = xS[tid];
    for (int k0 = 0; k0 < H; k0 += 16) {
        float av[16];
#pragma unroll
        for (int i = 0; i < 16; i++)
            av[i] = fmaxf(fmaf(x, w1S[k0 + i], b1S[k0 + i]), 0.f);
        store_a16(As, tid, av);
        load_w128(Bs, W2, H, k0, n0, tid);
        __syncthreads();
        mma_k8w(acc, As, Bs, 0, wy, wx, lane);
        mma_k8w(acc, As, Bs, 8, wy, wx, lane);
        __syncthreads();
    }

    int g = lane >> 2, t4 = lane & 3;
#pragma unroll
    for (int mt = 0; mt < 4; mt++)
#pragma unroll
        for (int half = 0; half < 2; half++) {
            int rl = wy * 64 + mt * 16 + g + half * 8;
            int row = m0 + rl;
            if (row >= EN) continue;
            float tb = tS[rl];
            const float* bep = &bond_emb[eS[rl] * H];
            size_t obase = (size_t)pS[rl] * H;
#pragma unroll
            for (int nt = 0; nt < 8; nt++) {
                int col = n0 + wx * 64 + nt * 8 + 2 * t4;
                float v0 = (acc[mt][nt][half * 2 + 0] + b2[col] + tb) * bep[col];
                float v1 = (acc[mt][nt][half * 2 + 1] + b2[col + 1] + tb) * bep[col + 1];
                *(float2*)&g_bond[obase + col] = make_float2(v0, v1);
            }
        }
}

// ---------------- GIN GEMMs -------------------------------------------------
// MODE 0: g_tmp = relu((g_h+g_aggr)@W + b)
// MODE 1: g_h   = maybe_relu(g_tmp@W + b) + g_h
template <int MODE>
__global__ void __launch_bounds__(128)
gin_mma(const float* __restrict__ W, const float* __restrict__ bias, int reluOut) {
    __shared__ float As[16 * PADW], Bs[16 * PADW];
    int tid = threadIdx.x, lane = tid & 31, warp = tid >> 5;
    int wy = warp >> 1, wx = warp & 1;
    int m0 = blockIdx.y * 128, n0 = blockIdx.x * 128;
    float acc[4][8][4] = {};
    int arow = m0 + tid;
    const float* A1 = (MODE == 0) ? g_h : g_tmp;

    for (int k0 = 0; k0 < H; k0 += 16) {
        float av[16];
        if (arow < NN) {
            const float* p = &A1[arow * H + k0];
#pragma unroll
            for (int j = 0; j < 4; j++) {
                float4 v = *(const float4*)(p + j * 4);
                av[j * 4 + 0] = v.x; av[j * 4 + 1] = v.y;
                av[j * 4 + 2] = v.z; av[j * 4 + 3] = v.w;
            }
            if (MODE == 0) {
                const float* q = &g_aggr[arow * H + k0];
#pragma unroll
                for (int j = 0; j < 4; j++) {
                    float4 v = *(const float4*)(q + j * 4);
                    av[j * 4 + 0] += v.x; av[j * 4 + 1] += v.y;
                    av[j * 4 + 2] += v.z; av[j * 4 + 3] += v.w;
                }
            }
        } else {
#pragma unroll
            for (int i = 0; i < 16; i++) av[i] = 0.f;
        }
        store_a16(As, tid, av);
        load_w128(Bs, W, H, k0, n0, tid);
        __syncthreads();
        mma_k8w(acc, As, Bs, 0, wy, wx, lane);
        mma_k8w(acc, As, Bs, 8, wy, wx, lane);
        __syncthreads();
    }

    int g = lane >> 2, t4 = lane & 3;
#pragma unroll
    for (int mt = 0; mt < 4; mt++)
#pragma unroll
        for (int half = 0; half < 2; half++) {
            int row = m0 + wy * 64 + mt * 16 + g + half * 8;
            if (row >= NN) continue;
#pragma unroll
            for (int nt = 0; nt < 8; nt++) {
                int col = n0 + wx * 64 + nt * 8 + 2 * t4;
                float v0 = acc[mt][nt][half * 2 + 0] + bias[col];
                float v1 = acc[mt][nt][half * 2 + 1] + bias[col + 1];
                if (reluOut) { v0 = fmaxf(v0, 0.f); v1 = fmaxf(v1, 0.f); }
                if (MODE == 0) {
                    *(float2*)&g_tmp[row * H + col] = make_float2(v0, v1);
                } else {
                    float2 rh = *(const float2*)&g_h[row * H + col];
                    *(float2*)&g_h[row * H + col] = make_float2(v0 + rh.x, v1 + rh.y);
                }
            }
        }
}

// ---------------- out layer 1: g_h1 = relu(feat@W1 + b1)  (K=512) -----------
__global__ void __launch_bounds__(128)
out1(const int* __restrict__ src, const int* __restrict__ dst,
     const float* __restrict__ W1, const float* __restrict__ b1) {
    __shared__ float As[16 * PADW], Bs[16 * PADW];
    __shared__ int srcS[128], dstS[128], pS[128];
    int tid = threadIdx.x, lane = tid & 31, warp = tid >> 5;
    int wy = warp >> 1, wx = warp & 1;
    int m0 = blockIdx.y * 128, n0 = blockIdx.x * 128;

    {
        int e = m0 + tid;
        int s = 0, d = 0, ps = 0;
        if (e < EN) { s = src[e]; d = dst[e]; ps = g_pos[e]; }
        srcS[tid] = s; dstS[tid] = d; pS[tid] = ps;
    }
    __syncthreads();

    float acc[4][8][4] = {};
    int e = m0 + tid;
    bool valid = (e < EN);

    for (int k0 = 0; k0 < 512; k0 += 16) {
        float av[16];
        if (k0 < 256) {
            const float* hs = &g_h[srcS[tid] * H + k0];
            const float* hd = &g_h[dstS[tid] * H + k0];
#pragma unroll
            for (int j = 0; j < 4; j++) {
                float4 a = *(const float4*)(hs + j * 4);
                float4 c = *(const float4*)(hd + j * 4);
                av[j * 4 + 0] = a.x * c.x; av[j * 4 + 1] = a.y * c.y;
                av[j * 4 + 2] = a.z * c.z; av[j * 4 + 3] = a.w * c.w;
            }
        } else if (valid) {
            const float* bp = &g_bond[(size_t)pS[tid] * H + (k0 - 256)];
#pragma unroll
            for (int j = 0; j < 4; j++) {
                float4 v = *(const float4*)(bp + j * 4);
                av[j * 4 + 0] = v.x; av[j * 4 + 1] = v.y;
                av[j * 4 + 2] = v.z; av[j * 4 + 3] = v.w;
            }
        } else {
#pragma unroll
            for (int i = 0; i < 16; i++) av[i] = 0.f;
        }
        store_a16(As, tid, av);
        load_w128(Bs, W1, H, k0, n0, tid);
        __syncthreads();
        mma_k8w(acc, As, Bs, 0, wy, wx, lane);
        mma_k8w(acc, As, Bs, 8, wy, wx, lane);
        __syncthreads();
    }

    int g = lane >> 2, t4 = lane & 3;
#pragma unroll
    for (int mt = 0; mt < 4; mt++)
#pragma unroll
        for (int half = 0; half < 2; half++) {
            int row = m0 + wy * 64 + mt * 16 + g + half * 8;
            if (row >= EN) continue;
#pragma unroll
            for (int nt = 0; nt < 8; nt++) {
                int col = n0 + wx * 64 + nt * 8 + 2 * t4;
                float v0 = fmaxf(acc[mt][nt][half * 2 + 0] + b1[col], 0.f);
                float v1 = fmaxf(acc[mt][nt][half * 2 + 1] + b1[col + 1], 0.f);
                *(float2*)&g_h1[(size_t)row * H + col] = make_float2(v0, v1);
            }
        }
}

// ---------------- out layers 2+3 fused --------------------------------------
__global__ void __launch_bounds__(128)
out23(const float* __restrict__ W2, const float* __restrict__ b2,
      const float* __restrict__ W3, const float* __restrict__ b3,
      float* __restrict__ out) {
    __shared__ float As[16 * PADW], Bs[16 * PADW];
    __shared__ float red[128 * 8];
    __shared__ float b2S[128], w3S[128];
    int tid = threadIdx.x, lane = tid & 31, warp = tid >> 5;
    int wy = warp >> 1, wx = warp & 1;
    int m0 = blockIdx.x * 128;

    b2S[tid] = b2[tid]; w3S[tid] = W3[tid];
    __syncthreads();

    float acc[4][8][4] = {};
    int e = m0 + tid;
    bool valid = (e < EN);

    for (int k0 = 0; k0 < H; k0 += 16) {
        float av[16];
        if (valid) {
            const float* p = &g_h1[(size_t)e * H + k0];
#pragma unroll
            for (int j = 0; j < 4; j++) {
                float4 v = *(const float4*)(p + j * 4);
                av[j * 4 + 0] = v.x; av[j * 4 + 1] = v.y;
                av[j * 4 + 2] = v.z; av[j * 4 + 3] = v.w;
            }
        } else {
#pragma unroll
            for (int i = 0; i < 16; i++) av[i] = 0.f;
        }
        store_a16(As, tid, av);
        load_w128(Bs, W2, 128, k0, 0, tid);
        __syncthreads();
        mma_k8w(acc, As, Bs, 0, wy, wx, lane);
        mma_k8w(acc, As, Bs, 8, wy, wx, lane);
        __syncthreads();
    }

    int g = lane >> 2, t4 = lane & 3;
#pragma unroll
    for (int mt = 0; mt < 4; mt++)
#pragma unroll
        for (int half = 0; half < 2; half++) {
            int rl = wy * 64 + mt * 16 + g + half * 8;
            float partial = 0.f;
#pragma unroll
            for (int nt = 0; nt < 8; nt++) {
                int col = wx * 64 + nt * 8 + 2 * t4;
                float h0 = fmaxf(acc[mt][nt][half * 2 + 0] + b2S[col], 0.f);
                float h1 = fmaxf(acc[mt][nt][half * 2 + 1] + b2S[col + 1], 0.f);
                partial += h0 * w3S[col] + h1 * w3S[col + 1];
            }
            red[rl * 8 + wx * 4 + t4] = partial;
        }
    __syncthreads();

    {
        int ee = m0 + tid;
        if (ee < EN) {
            float s = 0.f;
#pragma unroll
            for (int i = 0; i < 8; i++) s += red[tid * 8 + i];
            out[ee] = (s + b3[0]) * g_einv[ee];
        }
    }
}

// ---------------- launch ----------------------------------------------------
extern "C" void kernel_launch(void* const* d_in, const int* in_sizes, int n_in,
                              void* d_out, int out_size) {
    const int*   node_type = (const int*)d_in[0];
    const int*   edge_type = (const int*)d_in[1];
    const int*   edge_index = (const int*)d_in[2];
    const int*   batch = (const int*)d_in[3];
    const float* elen = (const float*)d_in[4];
    const float* t = (const float*)d_in[5];
    const float* atom_emb = (const float*)d_in[6];
    const float* bond_emb = (const float*)d_in[7];
    const float* in_W1 = (const float*)d_in[8];
    const float* in_b1 = (const float*)d_in[9];
    const float* in_W2 = (const float*)d_in[10];
    const float* in_b2 = (const float*)d_in[11];
    const float* fourier_W = (const float*)d_in[12];
    const float* temb_W = (const float*)d_in[13];
    const float* temb_b = (const float*)d_in[14];
    const float* d1W = (const float*)d_in[15];
    const float* d1b = (const float*)d_in[16];
    const float* gin_W1 = (const float*)d_in[17];
    const float* gin_b1 = (const float*)d_in[18];
    const float* gin_W2 = (const float*)d_in[19];
    const float* gin_b2 = (const float*)d_in[20];
    const float* out_W1 = (const float*)d_in[21];
    const float* out_b1 = (const float*)d_in[22];
    const float* out_W2 = (const float*)d_in[23];
    const float* out_b2 = (const float*)d_in[24];
    const float* out_W3 = (const float*)d_in[25];
    const float* out_b3 = (const float*)d_in[26];
    const int* src = edge_index;
    const int* dst = edge_index + EN;
    float* out = (float*)d_out;

    const int EB = (EN + 127) / 128;   // 2344
    const int NB = (NN + 127) / 128;   // 391

    init_h<<<(NN * 64 + 255) / 256, 256>>>(node_type, atom_emb);
    comb_kernel<<<1, 256>>>(temb_W, temb_b, d1W, d1b);
    temb_kernel<<<GN, 128>>>(t, fourier_W);

    // sort edges by dst
    zero_cnt<<<(NN + 255) / 256, 256>>>();
    hist<<<(EN + 255) / 256, 256>>>(dst);
    scan_kernel<<<1, 1024>>>();
    place<<<(EN + 255) / 256, 256>>>(src, dst);

    edge_bond<<<dim3(2, EB), 128>>>(elen, src, batch, edge_type,
                                    in_W1, in_b1, in_W2, in_b2, bond_emb);

    for (int c = 0; c < NCONV; c++) {
        gather<<<(NN + 7) / 8, 256>>>();
        gin_mma<0><<<dim3(2, NB), 128>>>(gin_W1 + c * H * H, gin_b1 + c * H, 1);
        gin_mma<1><<<dim3(2, NB), 128>>>(gin_W2 + c * H * H, gin_b2 + c * H,
                                         (c < NCONV - 1) ? 1 : 0);
    }

    out1<<<dim3(2, EB), 128>>>(src, dst, out_W1, out_b1);
    out23<<<EB, 128>>>(out_W2, out_b2, out_W3, out_b3, out);
}

// round 6
// speedup vs baseline: 2.2777x; 1.1141x over previous
#include <cuda_runtime.h>
#include <math.h>
#include <stdint.h>

#define EN 300000
#define NN 50000
#define GN 1024
#define H  256
#define NCONV 4
#define PA 132      // A smem row stride (128 + pad)
#define PB 260      // B smem row stride for 256-wide tiles
#define PB1 132     // B smem row stride for 128-wide tiles

// ---------------- scratch (device globals) ---------------------------------
static __device__ float g_bond[(size_t)EN * H];   // bond_attr [E,H] (edge order)
static __device__ float g_h1[(size_t)EN * H];     // out-MLP hidden1
static __device__ float g_h[NN * H];
static __device__ float g_aggr[NN * H];
static __device__ float g_tmp[NN * H];
static __device__ float g_temb[GN];
static __device__ float g_invstd[GN];
static __device__ float g_einv[EN];
// sort machinery
static __device__ int g_cnt[NN];      // zero-initialized; scan re-zeroes each call
static __device__ int g_rp[NN + 1];
static __device__ int g_woff[NN];
static __device__ int g_srcp[EN];     // sorted pos -> src node
static __device__ int g_eid[EN];      // sorted pos -> edge id

// ---------------- helpers ---------------------------------------------------
__device__ __forceinline__ float totf(float x) {
    uint32_t u; asm("cvt.rna.tf32.f32 %0, %1;" : "=r"(u) : "f"(x));
    return __uint_as_float(u);
}

// warp computes 64x64 via 32 mma m16n8k8 per k8 step
template <int BS>
__device__ __forceinline__ void mma_k8w(float acc[4][8][4],
                                        const float* As, const float* Bs,
                                        int kk, int wy, int wx, int lane) {
    int g = lane >> 2, t4 = lane & 3;
    float a[4][4];
#pragma unroll
    for (int mt = 0; mt < 4; mt++) {
        int rm = wy * 64 + mt * 16 + g;
        a[mt][0] = As[(kk + t4) * PA + rm];
        a[mt][1] = As[(kk + t4) * PA + rm + 8];
        a[mt][2] = As[(kk + t4 + 4) * PA + rm];
        a[mt][3] = As[(kk + t4 + 4) * PA + rm + 8];
    }
#pragma unroll
    for (int nt = 0; nt < 8; nt++) {
        int cn = wx * 64 + nt * 8 + g;
        float b0 = Bs[(kk + t4) * BS + cn];
        float b1 = Bs[(kk + t4 + 4) * BS + cn];
#pragma unroll
        for (int mt = 0; mt < 4; mt++) {
            asm volatile(
                "mma.sync.aligned.m16n8k8.row.col.f32.tf32.tf32.f32 "
                "{%0,%1,%2,%3}, {%4,%5,%6,%7}, {%8,%9}, {%0,%1,%2,%3};\n"
                : "+f"(acc[mt][nt][0]), "+f"(acc[mt][nt][1]),
                  "+f"(acc[mt][nt][2]), "+f"(acc[mt][nt][3])
                : "r"(__float_as_uint(a[mt][0])), "r"(__float_as_uint(a[mt][1])),
                  "r"(__float_as_uint(a[mt][2])), "r"(__float_as_uint(a[mt][3])),
                  "r"(__float_as_uint(b0)), "r"(__float_as_uint(b1)));
        }
    }
}

// B tile 16x256, 256 threads: 16 floats/thread
__device__ __forceinline__ void load_w256(float v[16], const float* __restrict__ W,
                                          int ldw, int k0, int tid) {
    int kr = tid >> 4, nq = (tid & 15) * 16;
    const float* p = &W[(size_t)(k0 + kr) * ldw + nq];
#pragma unroll
    for (int j = 0; j < 4; j++) {
        float4 t = *(const float4*)(p + 4 * j);
        v[4 * j] = t.x; v[4 * j + 1] = t.y; v[4 * j + 2] = t.z; v[4 * j + 3] = t.w;
    }
}
__device__ __forceinline__ void store_w256(float* Bs, const float v[16], int tid) {
    int kr = tid >> 4, nq = (tid & 15) * 16;
    float* d = &Bs[kr * PB + nq];
#pragma unroll
    for (int i = 0; i < 16; i++) d[i] = totf(v[i]);
}
// B tile 16x128, 128 threads
__device__ __forceinline__ void load_w128(float v[16], const float* __restrict__ W,
                                          int ldw, int k0, int tid) {
    int kr = tid >> 3, nq = (tid & 7) * 16;
    const float* p = &W[(size_t)(k0 + kr) * ldw + nq];
#pragma unroll
    for (int j = 0; j < 4; j++) {
        float4 t = *(const float4*)(p + 4 * j);
        v[4 * j] = t.x; v[4 * j + 1] = t.y; v[4 * j + 2] = t.z; v[4 * j + 3] = t.w;
    }
}
__device__ __forceinline__ void store_w128(float* Bs, const float v[16], int tid) {
    int kr = tid >> 3, nq = (tid & 7) * 16;
    float* d = &Bs[kr * PB1 + nq];
#pragma unroll
    for (int i = 0; i < 16; i++) d[i] = totf(v[i]);
}
// A: 256 threads, thread covers 8 k's of row r = tid>>1
__device__ __forceinline__ void store_a8(float* As, int kh, int r, const float v[8]) {
#pragma unroll
    for (int i = 0; i < 8; i++) As[(kh + i) * PA + r] = totf(v[i]);
}
// A: 128 threads, 16 k's of row tid
__device__ __forceinline__ void store_a16(float* As, int r, const float v[16]) {
#pragma unroll
    for (int k = 0; k < 16; k++) As[k * PA + r] = totf(v[k]);
}

// ---------------- temb (comb fused, coalesced) ------------------------------
__global__ void __launch_bounds__(128)
temb_fused(const float* __restrict__ t, const float* __restrict__ fw,
           const float* __restrict__ tW, const float* __restrict__ tb,
           const float* __restrict__ d1W, const float* __restrict__ d1b) {
    __shared__ float d1S[H], combS[H + 1], red[128];
    int tid = threadIdx.x, lane = tid & 31, warp = tid >> 5;
    d1S[tid] = d1W[tid]; d1S[tid + 128] = d1W[tid + 128];
    __syncthreads();
    for (int row = warp; row < H + 1; row += 4) {
        const float* p = (row < H) ? &tW[(size_t)row * H] : tb;
        float s = 0.f;
        for (int k = lane; k < H; k += 32) s += p[k] * d1S[k];
#pragma unroll
        for (int o = 16; o; o >>= 1) s += __shfl_down_sync(0xffffffffu, s, o);
        if (lane == 0) combS[row] = (row == H) ? s + d1b[0] : s;
    }
    __syncthreads();
    int g = blockIdx.x;
    float tt = t[g];
    float xp = tt * fw[tid] * 6.283185307179586f;
    red[tid] = sinf(xp) * combS[tid] + cosf(xp) * combS[128 + tid];
    __syncthreads();
    for (int s = 64; s > 0; s >>= 1) {
        if (tid < s) red[tid] += red[tid + s];
        __syncthreads();
    }
    if (tid == 0) {
        g_temb[g] = red[0] + combS[H];
        const float LS = 3.2188758248682006f;   // ln(25)
        float var = (expf(2.f * tt * LS) - 1.f) / (2.f * LS);
        g_invstd[g] = rsqrtf(var);
    }
}

// ---------------- sort machinery ---------------------------------------------
__global__ void __launch_bounds__(256) hist(const int* __restrict__ dst) {
    int e = blockIdx.x * blockDim.x + threadIdx.x;
    if (e < EN) atomicAdd(&g_cnt[dst[e]], 1);
}

__global__ void __launch_bounds__(1024) scan_kernel() {
    __shared__ int part[1024];
    const int CH = 49;
    int t = threadIdx.x;
    int beg = t * CH, end = min(beg + CH, NN);
    int s = 0;
    for (int i = beg; i < end; i++) s += g_cnt[i];
    part[t] = s;
    __syncthreads();
    for (int off = 1; off < 1024; off <<= 1) {
        int v = (t >= off) ? part[t - off] : 0;
        __syncthreads();
        part[t] += v;
        __syncthreads();
    }
    int run = (t == 0) ? 0 : part[t - 1];
    for (int i = beg; i < end; i++) {
        g_rp[i] = run; g_woff[i] = run; run += g_cnt[i];
        g_cnt[i] = 0;               // reset for next call (determinism)
    }
    if (t == 1023) g_rp[NN] = part[1023];
}

__global__ void __launch_bounds__(256) place(const int* __restrict__ src,
                                             const int* __restrict__ dst) {
    int e = blockIdx.x * blockDim.x + threadIdx.x;
    if (e >= EN) return;
    int p = atomicAdd(&g_woff[dst[e]], 1);
    g_srcp[p] = src[e];
    g_eid[p] = e;
}

__global__ void __launch_bounds__(256) init_h(const int* __restrict__ nt,
                                              const float* __restrict__ atom_emb) {
    int idx = blockIdx.x * blockDim.x + threadIdx.x;
    if (idx >= NN * 64) return;
    int n = idx >> 6, q = idx & 63;
    ((float4*)g_h)[idx] = ((const float4*)atom_emb)[nt[n] * 64 + q];
}

// ---------------- gather: aggr[n] = sum relu(h[src]+bond) -------------------
__global__ void __launch_bounds__(256) gather() {
    int warp = threadIdx.x >> 5, lane = threadIdx.x & 31;
    int n = blockIdx.x * 8 + warp;
    if (n >= NN) return;
    int q = lane * 8;
    float4 a0 = make_float4(0.f, 0.f, 0.f, 0.f), a1 = a0;
    int beg = g_rp[n], end = g_rp[n + 1];
    for (int p = beg; p < end; p++) {
        int s = g_srcp[p];
        int e = g_eid[p];
        const float4* hp = (const float4*)&g_h[s * H + q];
        const float4* bp = (const float4*)&g_bond[(size_t)e * H + q];
        float4 h0 = hp[0], h1v = hp[1], b0 = bp[0], b1v = bp[1];
        a0.x += fmaxf(h0.x + b0.x, 0.f);  a0.y += fmaxf(h0.y + b0.y, 0.f);
        a0.z += fmaxf(h0.z + b0.z, 0.f);  a0.w += fmaxf(h0.w + b0.w, 0.f);
        a1.x += fmaxf(h1v.x + b1v.x, 0.f); a1.y += fmaxf(h1v.y + b1v.y, 0.f);
        a1.z += fmaxf(h1v.z + b1v.z, 0.f); a1.w += fmaxf(h1v.w + b1v.w, 0.f);
    }
    float4* ap = (float4*)&g_aggr[n * H + q];
    ap[0] = a0; ap[1] = a1;
}

// ---------------- edge_bond: 128x256 tile, pipelined ------------------------
#define ASZ (16 * PA)
#define BSZ (16 * PB)
#define EB_SMEM ((2 * ASZ + 2 * BSZ + 128 + 128 + 128 + 2 * H) * 4)

__global__ void __launch_bounds__(256, 1)
edge_bond(const float* __restrict__ elen, const int* __restrict__ src,
          const int* __restrict__ batch, const int* __restrict__ etype,
          const float* __restrict__ W1, const float* __restrict__ b1,
          const float* __restrict__ W2, const float* __restrict__ b2,
          const float* __restrict__ bond_emb) {
    extern __shared__ float sm[];
    float* As = sm;                       // 2*ASZ
    float* Bs = sm + 2 * ASZ;             // 2*BSZ
    float* xS = Bs + 2 * BSZ;             // 128
    float* tS = xS + 128;                 // 128
    int*   eS = (int*)(tS + 128);         // 128
    float* w1S = (float*)(eS + 128);      // 256
    float* b1S = w1S + H;                 // 256

    int tid = threadIdx.x, lane = tid & 31, warp = tid >> 5;
    int wy = warp >> 2, wx = warp & 3;
    int m0 = blockIdx.x * 128;

    if (tid < 128) {
        int e = m0 + tid;
        float x = 0.f, tb = 0.f; int et = 0;
        if (e < EN) {
            x = elen[e];
            int gph = batch[src[e]];
            tb = g_temb[gph];
            g_einv[e] = g_invstd[gph];
            et = etype[e];
        }
        xS[tid] = x; tS[tid] = tb; eS[tid] = et;
    }
    w1S[tid] = W1[tid]; b1S[tid] = b1[tid];
    __syncthreads();

    int r = tid >> 1, kh = (tid & 1) * 8;
    float x = xS[r];
    float areg[8], breg[16];
    // prologue: step 0
#pragma unroll
    for (int i = 0; i < 8; i++)
        areg[i] = fmaxf(fmaf(x, w1S[kh + i], b1S[kh + i]), 0.f);
    load_w256(breg, W2, H, 0, tid);
    store_a8(As, kh, r, areg);
    store_w256(Bs, breg, tid);
    __syncthreads();

    float acc[4][8][4] = {};
    for (int s = 0; s < 16; s++) {
        int cur = s & 1, nxt = cur ^ 1;
        if (s < 15) {
            int k0 = (s + 1) * 16;
#pragma unroll
            for (int i = 0; i < 8; i++)
                areg[i] = fmaxf(fmaf(x, w1S[k0 + kh + i], b1S[k0 + kh + i]), 0.f);
            load_w256(breg, W2, H, k0, tid);
        }
        mma_k8w<PB>(acc, As + cur * ASZ, Bs + cur * BSZ, 0, wy, wx, lane);
        mma_k8w<PB>(acc, As + cur * ASZ, Bs + cur * BSZ, 8, wy, wx, lane);
        if (s < 15) {
            store_a8(As + nxt * ASZ, kh, r, areg);
            store_w256(Bs + nxt * BSZ, breg, tid);
            __syncthreads();
        }
    }

    int g = lane >> 2, t4 = lane & 3;
#pragma unroll
    for (int mt = 0; mt < 4; mt++)
#pragma unroll
        for (int half = 0; half < 2; half++) {
            int rl = wy * 64 + mt * 16 + g + half * 8;
            int row = m0 + rl;
            if (row >= EN) continue;
            float tb = tS[rl];
            const float* bep = &bond_emb[eS[rl] * H];
            size_t obase = (size_t)row * H;
#pragma unroll
            for (int nt = 0; nt < 8; nt++) {
                int col = wx * 64 + nt * 8 + 2 * t4;
                float v0 = (acc[mt][nt][half * 2 + 0] + b2[col] + tb) * bep[col];
                float v1 = (acc[mt][nt][half * 2 + 1] + b2[col + 1] + tb) * bep[col + 1];
                *(float2*)&g_bond[obase + col] = make_float2(v0, v1);
            }
        }
}

// ---------------- GIN GEMMs: 128x256 tile, pipelined ------------------------
#define GIN_SMEM ((2 * ASZ + 2 * BSZ) * 4)
template <int MODE>
__global__ void __launch_bounds__(256, 1)
gin_mma(const float* __restrict__ W, const float* __restrict__ bias, int reluOut) {
    extern __shared__ float sm[];
    float* As = sm;
    float* Bs = sm + 2 * ASZ;
    int tid = threadIdx.x, lane = tid & 31, warp = tid >> 5;
    int wy = warp >> 2, wx = warp & 3;
    int m0 = blockIdx.x * 128;
    int r = tid >> 1, kh = (tid & 1) * 8;
    int arow = m0 + r;
    bool valid = (arow < NN);
    const float* A1 = (MODE == 0) ? g_h : g_tmp;

    float areg[8], breg[16];
    auto loadA = [&](int k0) {
        if (valid) {
            const float* p = &A1[arow * H + k0 + kh];
            float4 v0 = *(const float4*)p, v1 = *(const float4*)(p + 4);
            areg[0] = v0.x; areg[1] = v0.y; areg[2] = v0.z; areg[3] = v0.w;
            areg[4] = v1.x; areg[5] = v1.y; areg[6] = v1.z; areg[7] = v1.w;
            if (MODE == 0) {
                const float* q = &g_aggr[arow * H + k0 + kh];
                float4 w0 = *(const float4*)q, w1 = *(const float4*)(q + 4);
                areg[0] += w0.x; areg[1] += w0.y; areg[2] += w0.z; areg[3] += w0.w;
                areg[4] += w1.x; areg[5] += w1.y; areg[6] += w1.z; areg[7] += w1.w;
            }
        } else {
#pragma unroll
            for (int i = 0; i < 8; i++) areg[i] = 0.f;
        }
    };

    loadA(0);
    load_w256(breg, W, H, 0, tid);
    store_a8(As, kh, r, areg);
    store_w256(Bs, breg, tid);
    __syncthreads();

    float acc[4][8][4] = {};
    for (int s = 0; s < 16; s++) {
        int cur = s & 1, nxt = cur ^ 1;
        if (s < 15) { loadA((s + 1) * 16); load_w256(breg, W, H, (s + 1) * 16, tid); }
        mma_k8w<PB>(acc, As + cur * ASZ, Bs + cur * BSZ, 0, wy, wx, lane);
        mma_k8w<PB>(acc, As + cur * ASZ, Bs + cur * BSZ, 8, wy, wx, lane);
        if (s < 15) {
            store_a8(As + nxt * ASZ, kh, r, areg);
            store_w256(Bs + nxt * BSZ, breg, tid);
            __syncthreads();
        }
    }

    int g = lane >> 2, t4 = lane & 3;
#pragma unroll
    for (int mt = 0; mt < 4; mt++)
#pragma unroll
        for (int half = 0; half < 2; half++) {
            int row = m0 + wy * 64 + mt * 16 + g + half * 8;
            if (row >= NN) continue;
#pragma unroll
            for (int nt = 0; nt < 8; nt++) {
                int col = wx * 64 + nt * 8 + 2 * t4;
                float v0 = acc[mt][nt][half * 2 + 0] + bias[col];
                float v1 = acc[mt][nt][half * 2 + 1] + bias[col + 1];
                if (reluOut) { v0 = fmaxf(v0, 0.f); v1 = fmaxf(v1, 0.f); }
                if (MODE == 0) {
                    *(float2*)&g_tmp[row * H + col] = make_float2(v0, v1);
                } else {
                    float2 rh = *(const float2*)&g_h[row * H + col];
                    *(float2*)&g_h[row * H + col] = make_float2(v0 + rh.x, v1 + rh.y);
                }
            }
        }
}

// ---------------- out1: K=512, 128x256 tile, pipelined ----------------------
#define OUT1_SMEM ((2 * ASZ + 2 * BSZ + 256) * 4)
__global__ void __launch_bounds__(256, 1)
out1(const int* __restrict__ src, const int* __restrict__ dst,
     const float* __restrict__ W1, const float* __restrict__ b1) {
    extern __shared__ float sm[];
    float* As = sm;
    float* Bs = sm + 2 * ASZ;
    int* srcS = (int*)(Bs + 2 * BSZ);   // 128
    int* dstS = srcS + 128;             // 128
    int tid = threadIdx.x, lane = tid & 31, warp = tid >> 5;
    int wy = warp >> 2, wx = warp & 3;
    int m0 = blockIdx.x * 128;

    if (tid < 128) {
        int e = m0 + tid;
        int s = 0, d = 0;
        if (e < EN) { s = src[e]; d = dst[e]; }
        srcS[tid] = s; dstS[tid] = d;
    }
    __syncthreads();

    int r = tid >> 1, kh = (tid & 1) * 8;
    int e = m0 + r;
    bool valid = (e < EN);
    float areg[8], breg[16];

    auto loadA = [&](int k0) {
        if (k0 < 256) {
            const float* hs = &g_h[srcS[r] * H + k0 + kh];
            const float* hd = &g_h[dstS[r] * H + k0 + kh];
            float4 a0 = *(const float4*)hs, a1 = *(const float4*)(hs + 4);
            float4 c0 = *(const float4*)hd, c1 = *(const float4*)(hd + 4);
            areg[0] = a0.x * c0.x; areg[1] = a0.y * c0.y;
            areg[2] = a0.z * c0.z; areg[3] = a0.w * c0.w;
            areg[4] = a1.x * c1.x; areg[5] = a1.y * c1.y;
            areg[6] = a1.z * c1.z; areg[7] = a1.w * c1.w;
        } else if (valid) {
            const float* bp = &g_bond[(size_t)e * H + (k0 - 256) + kh];
            float4 v0 = *(const float4*)bp, v1 = *(const float4*)(bp + 4);
            areg[0] = v0.x; areg[1] = v0.y; areg[2] = v0.z; areg[3] = v0.w;
            areg[4] = v1.x; areg[5] = v1.y; areg[6] = v1.z; areg[7] = v1.w;
        } else {
#pragma unroll
            for (int i = 0; i < 8; i++) areg[i] = 0.f;
        }
    };

    loadA(0);
    load_w256(breg, W1, H, 0, tid);
    store_a8(As, kh, r, areg);
    store_w256(Bs, breg, tid);
    __syncthreads();

    float acc[4][8][4] = {};
    for (int s = 0; s < 32; s++) {
        int cur = s & 1, nxt = cur ^ 1;
        if (s < 31) { loadA((s + 1) * 16); load_w256(breg, W1, H, (s + 1) * 16, tid); }
        mma_k8w<PB>(acc, As + cur * ASZ, Bs + cur * BSZ, 0, wy, wx, lane);
        mma_k8w<PB>(acc, As + cur * ASZ, Bs + cur * BSZ, 8, wy, wx, lane);
        if (s < 31) {
            store_a8(As + nxt * ASZ, kh, r, areg);
            store_w256(Bs + nxt * BSZ, breg, tid);
            __syncthreads();
        }
    }

    int g = lane >> 2, t4 = lane & 3;
#pragma unroll
    for (int mt = 0; mt < 4; mt++)
#pragma unroll
        for (int half = 0; half < 2; half++) {
            int row = m0 + wy * 64 + mt * 16 + g + half * 8;
            if (row >= EN) continue;
#pragma unroll
            for (int nt = 0; nt < 8; nt++) {
                int col = wx * 64 + nt * 8 + 2 * t4;
                float v0 = fmaxf(acc[mt][nt][half * 2 + 0] + b1[col], 0.f);
                float v1 = fmaxf(acc[mt][nt][half * 2 + 1] + b1[col + 1], 0.f);
                *(float2*)&g_h1[(size_t)row * H + col] = make_float2(v0, v1);
            }
        }
}

// ---------------- out23 fused: 128x128 tile, pipelined (static smem) --------
#define BSZ1 (16 * PB1)
__global__ void __launch_bounds__(128, 2)
out23(const float* __restrict__ W2, const float* __restrict__ b2,
      const float* __restrict__ W3, const float* __restrict__ b3,
      float* __restrict__ out) {
    __shared__ float As[2 * ASZ], Bs[2 * BSZ1];
    __shared__ float red[128 * 8];
    __shared__ float b2S[128], w3S[128];
    int tid = threadIdx.x, lane = tid & 31, warp = tid >> 5;
    int wy = warp >> 1, wx = warp & 1;
    int m0 = blockIdx.x * 128;

    b2S[tid] = b2[tid]; w3S[tid] = W3[tid];

    int e = m0 + tid;
    bool valid = (e < EN);
    float areg[16], breg[16];
    auto loadA = [&](int k0) {
        if (valid) {
            const float* p = &g_h1[(size_t)e * H + k0];
#pragma unroll
            for (int j = 0; j < 4; j++) {
                float4 v = *(const float4*)(p + 4 * j);
                areg[4 * j] = v.x; areg[4 * j + 1] = v.y;
                areg[4 * j + 2] = v.z; areg[4 * j + 3] = v.w;
            }
        } else {
#pragma unroll
            for (int i = 0; i < 16; i++) areg[i] = 0.f;
        }
    };

    loadA(0);
    load_w128(breg, W2, 128, 0, tid);
    store_a16(As, tid, areg);
    store_w128(Bs, breg, tid);
    __syncthreads();

    float acc[4][8][4] = {};
    for (int s = 0; s < 16; s++) {
        int cur = s & 1, nxt = cur ^ 1;
        if (s < 15) { loadA((s + 1) * 16); load_w128(breg, W2, 128, (s + 1) * 16, tid); }
        mma_k8w<PB1>(acc, As + cur * ASZ, Bs + cur * BSZ1, 0, wy, wx, lane);
        mma_k8w<PB1>(acc, As + cur * ASZ, Bs + cur * BSZ1, 8, wy, wx, lane);
        if (s < 15) {
            store_a16(As + nxt * ASZ, tid, areg);
            store_w128(Bs + nxt * BSZ1, breg, tid);
            __syncthreads();
        }
    }

    int g = lane >> 2, t4 = lane & 3;
#pragma unroll
    for (int mt = 0; mt < 4; mt++)
#pragma unroll
        for (int half = 0; half < 2; half++) {
            int rl = wy * 64 + mt * 16 + g + half * 8;
            float partial = 0.f;
#pragma unroll
            for (int nt = 0; nt < 8; nt++) {
                int col = wx * 64 + nt * 8 + 2 * t4;
                float h0 = fmaxf(acc[mt][nt][half * 2 + 0] + b2S[col], 0.f);
                float h1 = fmaxf(acc[mt][nt][half * 2 + 1] + b2S[col + 1], 0.f);
                partial += h0 * w3S[col] + h1 * w3S[col + 1];
            }
            red[rl * 8 + wx * 4 + t4] = partial;
        }
    __syncthreads();

    if (valid) {
        float s = 0.f;
#pragma unroll
        for (int i = 0; i < 8; i++) s += red[tid * 8 + i];
        out[e] = (s + b3[0]) * g_einv[e];
    }
}

// ---------------- launch ----------------------------------------------------
extern "C" void kernel_launch(void* const* d_in, const int* in_sizes, int n_in,
                              void* d_out, int out_size) {
    const int*   node_type = (const int*)d_in[0];
    const int*   edge_type = (const int*)d_in[1];
    const int*   edge_index = (const int*)d_in[2];
    const int*   batch = (const int*)d_in[3];
    const float* elen = (const float*)d_in[4];
    const float* t = (const float*)d_in[5];
    const float* atom_emb = (const float*)d_in[6];
    const float* bond_emb = (const float*)d_in[7];
    const float* in_W1 = (const float*)d_in[8];
    const float* in_b1 = (const float*)d_in[9];
    const float* in_W2 = (const float*)d_in[10];
    const float* in_b2 = (const float*)d_in[11];
    const float* fourier_W = (const float*)d_in[12];
    const float* temb_W = (const float*)d_in[13];
    const float* temb_b = (const float*)d_in[14];
    const float* d1W = (const float*)d_in[15];
    const float* d1b = (const float*)d_in[16];
    const float* gin_W1 = (const float*)d_in[17];
    const float* gin_b1 = (const float*)d_in[18];
    const float* gin_W2 = (const float*)d_in[19];
    const float* gin_b2 = (const float*)d_in[20];
    const float* out_W1 = (const float*)d_in[21];
    const float* out_b1 = (const float*)d_in[22];
    const float* out_W2 = (const float*)d_in[23];
    const float* out_b2 = (const float*)d_in[24];
    const float* out_W3 = (const float*)d_in[25];
    const float* out_b3 = (const float*)d_in[26];
    const int* src = edge_index;
    const int* dst = edge_index + EN;
    float* out = (float*)d_out;

    const int EB = (EN + 127) / 128;   // 2344
    const int NB = (NN + 127) / 128;   // 391

    static int attr_done = 0;
    if (!attr_done) {
        cudaFuncSetAttribute(edge_bond, cudaFuncAttributeMaxDynamicSharedMemorySize, EB_SMEM);
        cudaFuncSetAttribute(gin_mma<0>, cudaFuncAttributeMaxDynamicSharedMemorySize, GIN_SMEM);
        cudaFuncSetAttribute(gin_mma<1>, cudaFuncAttributeMaxDynamicSharedMemorySize, GIN_SMEM);
        cudaFuncSetAttribute(out1, cudaFuncAttributeMaxDynamicSharedMemorySize, OUT1_SMEM);
        attr_done = 1;
    }

    // launch order chosen so ncu (launch index 3) profiles edge_bond
    temb_fused<<<GN, 128>>>(t, fourier_W, temb_W, temb_b, d1W, d1b);      // 0
    hist<<<(EN + 255) / 256, 256>>>(dst);                                 // 1
    scan_kernel<<<1, 1024>>>();                                           // 2
    edge_bond<<<EB, 256, EB_SMEM>>>(elen, src, batch, edge_type,          // 3
                                    in_W1, in_b1, in_W2, in_b2, bond_emb);
    place<<<(EN + 255) / 256, 256>>>(src, dst);                           // 4
    init_h<<<(NN * 64 + 255) / 256, 256>>>(node_type, atom_emb);          // 5

    for (int c = 0; c < NCONV; c++) {
        gather<<<(NN + 7) / 8, 256>>>();
        gin_mma<0><<<NB, 256, GIN_SMEM>>>(gin_W1 + c * H * H, gin_b1 + c * H, 1);
        gin_mma<1><<<NB, 256, GIN_SMEM>>>(gin_W2 + c * H * H, gin_b2 + c * H,
                                          (c < NCONV - 1) ? 1 : 0);
    }

    out1<<<EB, 256, OUT1_SMEM>>>(src, dst, out_W1, out_b1);
    out23<<<EB, 128>>>(out_W2, out_b2, out_W3, out_b3, out);
}

// round 7
// speedup vs baseline: 2.4477x; 1.0746x over previous
#include <cuda_runtime.h>
#include <math.h>
#include <stdint.h>

#define EN 300000
#define NN 50000
#define GN 1024
#define H  256
#define NCONV 4
#define PA 136      // A smem row stride: 136 mod 32 == 8 -> conflict-free frag loads
#define PB 264      // B smem row stride (256-wide tiles): 264 mod 32 == 8
#define PB1 136     // B smem row stride (128-wide tiles)

// ---------------- scratch (device globals) ---------------------------------
static __device__ float g_bond[(size_t)EN * H];   // bond_attr [E,H] (edge order)
static __device__ float g_h1[(size_t)EN * H];     // out-MLP hidden1
static __device__ float g_h[NN * H];
static __device__ float g_aggr[NN * H];
static __device__ float g_tmp[NN * H];
static __device__ float g_temb[GN];
static __device__ float g_invstd[GN];
static __device__ float g_einv[EN];
// sort machinery
static __device__ int g_cnt[NN];      // zero-initialized; scan re-zeroes each call
static __device__ int g_rp[NN + 1];
static __device__ int g_woff[NN];
static __device__ int g_srcp[EN];     // sorted pos -> src node
static __device__ int g_eid[EN];      // sorted pos -> edge id

// ---------------- helpers ---------------------------------------------------
__device__ __forceinline__ float totf(float x) {
    uint32_t u; asm("cvt.rna.tf32.f32 %0, %1;" : "=r"(u) : "f"(x));
    return __uint_as_float(u);
}

// warp computes 64x64 via 32 mma m16n8k8 per k8 step
template <int BS>
__device__ __forceinline__ void mma_k8w(float acc[4][8][4],
                                        const float* As, const float* Bs,
                                        int kk, int wy, int wx, int lane) {
    int g = lane >> 2, t4 = lane & 3;
    float a[4][4];
#pragma unroll
    for (int mt = 0; mt < 4; mt++) {
        int rm = wy * 64 + mt * 16 + g;
        a[mt][0] = As[(kk + t4) * PA + rm];
        a[mt][1] = As[(kk + t4) * PA + rm + 8];
        a[mt][2] = As[(kk + t4 + 4) * PA + rm];
        a[mt][3] = As[(kk + t4 + 4) * PA + rm + 8];
    }
#pragma unroll
    for (int nt = 0; nt < 8; nt++) {
        int cn = wx * 64 + nt * 8 + g;
        float b0 = Bs[(kk + t4) * BS + cn];
        float b1 = Bs[(kk + t4 + 4) * BS + cn];
#pragma unroll
        for (int mt = 0; mt < 4; mt++) {
            asm volatile(
                "mma.sync.aligned.m16n8k8.row.col.f32.tf32.tf32.f32 "
                "{%0,%1,%2,%3}, {%4,%5,%6,%7}, {%8,%9}, {%0,%1,%2,%3};\n"
                : "+f"(acc[mt][nt][0]), "+f"(acc[mt][nt][1]),
                  "+f"(acc[mt][nt][2]), "+f"(acc[mt][nt][3])
                : "r"(__float_as_uint(a[mt][0])), "r"(__float_as_uint(a[mt][1])),
                  "r"(__float_as_uint(a[mt][2])), "r"(__float_as_uint(a[mt][3])),
                  "r"(__float_as_uint(b0)), "r"(__float_as_uint(b1)));
        }
    }
}

// B tile 16x256, 256 threads: 16 floats/thread
__device__ __forceinline__ void load_w256(float v[16], const float* __restrict__ W,
                                          int ldw, int k0, int tid) {
    int kr = tid >> 4, nq = (tid & 15) * 16;
    const float* p = &W[(size_t)(k0 + kr) * ldw + nq];
#pragma unroll
    for (int j = 0; j < 4; j++) {
        float4 t = *(const float4*)(p + 4 * j);
        v[4 * j] = t.x; v[4 * j + 1] = t.y; v[4 * j + 2] = t.z; v[4 * j + 3] = t.w;
    }
}
__device__ __forceinline__ void store_w256(float* Bs, const float v[16], int tid) {
    int kr = tid >> 4, nq = (tid & 15) * 16;
    float* d = &Bs[kr * PB + nq];
#pragma unroll
    for (int i = 0; i < 16; i++) d[i] = totf(v[i]);
}
// B tile 16x128, 128 threads
__device__ __forceinline__ void load_w128(float v[16], const float* __restrict__ W,
                                          int ldw, int k0, int tid) {
    int kr = tid >> 3, nq = (tid & 7) * 16;
    const float* p = &W[(size_t)(k0 + kr) * ldw + nq];
#pragma unroll
    for (int j = 0; j < 4; j++) {
        float4 t = *(const float4*)(p + 4 * j);
        v[4 * j] = t.x; v[4 * j + 1] = t.y; v[4 * j + 2] = t.z; v[4 * j + 3] = t.w;
    }
}
__device__ __forceinline__ void store_w128(float* Bs, const float v[16], int tid) {
    int kr = tid >> 3, nq = (tid & 7) * 16;
    float* d = &Bs[kr * PB1 + nq];
#pragma unroll
    for (int i = 0; i < 16; i++) d[i] = totf(v[i]);
}
// A: 256 threads, thread covers 8 k's of row r = tid>>1
__device__ __forceinline__ void store_a8(float* As, int kh, int r, const float v[8]) {
#pragma unroll
    for (int i = 0; i < 8; i++) As[(kh + i) * PA + r] = totf(v[i]);
}
// A: 128 threads, 16 k's of row tid
__device__ __forceinline__ void store_a16(float* As, int r, const float v[16]) {
#pragma unroll
    for (int k = 0; k < 16; k++) As[k * PA + r] = totf(v[k]);
}

// ---------------- temb (comb fused, coalesced) ------------------------------
__global__ void __launch_bounds__(128)
temb_fused(const float* __restrict__ t, const float* __restrict__ fw,
           const float* __restrict__ tW, const float* __restrict__ tb,
           const float* __restrict__ d1W, const float* __restrict__ d1b) {
    __shared__ float d1S[H], combS[H + 1], red[128];
    int tid = threadIdx.x, lane = tid & 31, warp = tid >> 5;
    d1S[tid] = d1W[tid]; d1S[tid + 128] = d1W[tid + 128];
    __syncthreads();
    for (int row = warp; row < H + 1; row += 4) {
        const float* p = (row < H) ? &tW[(size_t)row * H] : tb;
        float s = 0.f;
        for (int k = lane; k < H; k += 32) s += p[k] * d1S[k];
#pragma unroll
        for (int o = 16; o; o >>= 1) s += __shfl_down_sync(0xffffffffu, s, o);
        if (lane == 0) combS[row] = (row == H) ? s + d1b[0] : s;
    }
    __syncthreads();
    int g = blockIdx.x;
    float tt = t[g];
    float xp = tt * fw[tid] * 6.283185307179586f;
    red[tid] = sinf(xp) * combS[tid] + cosf(xp) * combS[128 + tid];
    __syncthreads();
    for (int s = 64; s > 0; s >>= 1) {
        if (tid < s) red[tid] += red[tid + s];
        __syncthreads();
    }
    if (tid == 0) {
        g_temb[g] = red[0] + combS[H];
        const float LS = 3.2188758248682006f;   // ln(25)
        float var = (expf(2.f * tt * LS) - 1.f) / (2.f * LS);
        g_invstd[g] = rsqrtf(var);
    }
}

// ---------------- sort machinery ---------------------------------------------
__global__ void __launch_bounds__(256) hist(const int* __restrict__ dst) {
    int e = blockIdx.x * blockDim.x + threadIdx.x;
    if (e < EN) atomicAdd(&g_cnt[dst[e]], 1);
}

__global__ void __launch_bounds__(1024) scan_kernel() {
    __shared__ int part[1024];
    const int CH = 49;
    int t = threadIdx.x;
    int beg = t * CH, end = min(beg + CH, NN);
    int s = 0;
    for (int i = beg; i < end; i++) s += g_cnt[i];
    part[t] = s;
    __syncthreads();
    for (int off = 1; off < 1024; off <<= 1) {
        int v = (t >= off) ? part[t - off] : 0;
        __syncthreads();
        part[t] += v;
        __syncthreads();
    }
    int run = (t == 0) ? 0 : part[t - 1];
    for (int i = beg; i < end; i++) {
        g_rp[i] = run; g_woff[i] = run; run += g_cnt[i];
        g_cnt[i] = 0;               // reset for next call (determinism)
    }
    if (t == 1023) g_rp[NN] = part[1023];
}

__global__ void __launch_bounds__(256) place(const int* __restrict__ src,
                                             const int* __restrict__ dst) {
    int e = blockIdx.x * blockDim.x + threadIdx.x;
    if (e >= EN) return;
    int p = atomicAdd(&g_woff[dst[e]], 1);
    g_srcp[p] = src[e];
    g_eid[p] = e;
}

__global__ void __launch_bounds__(256) init_h(const int* __restrict__ nt,
                                              const float* __restrict__ atom_emb) {
    int idx = blockIdx.x * blockDim.x + threadIdx.x;
    if (idx >= NN * 64) return;
    int n = idx >> 6, q = idx & 63;
    ((float4*)g_h)[idx] = ((const float4*)atom_emb)[nt[n] * 64 + q];
}

// ---------------- gather: aggr[n] = sum relu(h[src]+bond) -------------------
__global__ void __launch_bounds__(256) gather() {
    int warp = threadIdx.x >> 5, lane = threadIdx.x & 31;
    int n = blockIdx.x * 8 + warp;
    if (n >= NN) return;
    int q = lane * 8;
    float4 a0 = make_float4(0.f, 0.f, 0.f, 0.f), a1 = a0;
    int beg = g_rp[n], end = g_rp[n + 1];
    for (int p = beg; p < end; p++) {
        int s = g_srcp[p];
        int e = g_eid[p];
        const float4* hp = (const float4*)&g_h[s * H + q];
        const float4* bp = (const float4*)&g_bond[(size_t)e * H + q];
        float4 h0 = hp[0], h1v = hp[1], b0 = bp[0], b1v = bp[1];
        a0.x += fmaxf(h0.x + b0.x, 0.f);  a0.y += fmaxf(h0.y + b0.y, 0.f);
        a0.z += fmaxf(h0.z + b0.z, 0.f);  a0.w += fmaxf(h0.w + b0.w, 0.f);
        a1.x += fmaxf(h1v.x + b1v.x, 0.f); a1.y += fmaxf(h1v.y + b1v.y, 0.f);
        a1.z += fmaxf(h1v.z + b1v.z, 0.f); a1.w += fmaxf(h1v.w + b1v.w, 0.f);
    }
    float4* ap = (float4*)&g_aggr[n * H + q];
    ap[0] = a0; ap[1] = a1;
}

// ---------------- edge_bond: 128x256 tile, pipelined ------------------------
#define ASZ (16 * PA)
#define BSZ (16 * PB)
#define EB_SMEM ((2 * ASZ + 2 * BSZ + 128 + 128 + 128 + 2 * H) * 4)

__global__ void __launch_bounds__(256, 1)
edge_bond(const float* __restrict__ elen, const int* __restrict__ src,
          const int* __restrict__ batch, const int* __restrict__ etype,
          const float* __restrict__ W1, const float* __restrict__ b1,
          const float* __restrict__ W2, const float* __restrict__ b2,
          const float* __restrict__ bond_emb) {
    extern __shared__ float sm[];
    float* As = sm;                       // 2*ASZ
    float* Bs = sm + 2 * ASZ;             // 2*BSZ
    float* xS = Bs + 2 * BSZ;             // 128
    float* tS = xS + 128;                 // 128
    int*   eS = (int*)(tS + 128);         // 128
    float* w1S = (float*)(eS + 128);      // 256
    float* b1S = w1S + H;                 // 256

    int tid = threadIdx.x, lane = tid & 31, warp = tid >> 5;
    int wy = warp >> 2, wx = warp & 3;
    int m0 = blockIdx.x * 128;

    if (tid < 128) {
        int e = m0 + tid;
        float x = 0.f, tb = 0.f; int et = 0;
        if (e < EN) {
            x = elen[e];
            int gph = batch[src[e]];
            tb = g_temb[gph];
            g_einv[e] = g_invstd[gph];
            et = etype[e];
        }
        xS[tid] = x; tS[tid] = tb; eS[tid] = et;
    }
    w1S[tid] = W1[tid]; b1S[tid] = b1[tid];
    __syncthreads();

    int r = tid >> 1, kh = (tid & 1) * 8;
    float x = xS[r];
    float areg[8], breg[16];
    // prologue: step 0
#pragma unroll
    for (int i = 0; i < 8; i++)
        areg[i] = fmaxf(fmaf(x, w1S[kh + i], b1S[kh + i]), 0.f);
    load_w256(breg, W2, H, 0, tid);
    store_a8(As, kh, r, areg);
    store_w256(Bs, breg, tid);
    __syncthreads();

    float acc[4][8][4] = {};
    for (int s = 0; s < 16; s++) {
        int cur = s & 1, nxt = cur ^ 1;
        if (s < 15) {
            int k0 = (s + 1) * 16;
#pragma unroll
            for (int i = 0; i < 8; i++)
                areg[i] = fmaxf(fmaf(x, w1S[k0 + kh + i], b1S[k0 + kh + i]), 0.f);
            load_w256(breg, W2, H, k0, tid);
        }
        mma_k8w<PB>(acc, As + cur * ASZ, Bs + cur * BSZ, 0, wy, wx, lane);
        mma_k8w<PB>(acc, As + cur * ASZ, Bs + cur * BSZ, 8, wy, wx, lane);
        if (s < 15) {
            store_a8(As + nxt * ASZ, kh, r, areg);
            store_w256(Bs + nxt * BSZ, breg, tid);
            __syncthreads();
        }
    }

    int g = lane >> 2, t4 = lane & 3;
#pragma unroll
    for (int mt = 0; mt < 4; mt++)
#pragma unroll
        for (int half = 0; half < 2; half++) {
            int rl = wy * 64 + mt * 16 + g + half * 8;
            int row = m0 + rl;
            if (row >= EN) continue;
            float tb = tS[rl];
            const float* bep = &bond_emb[eS[rl] * H];
            size_t obase = (size_t)row * H;
#pragma unroll
            for (int nt = 0; nt < 8; nt++) {
                int col = wx * 64 + nt * 8 + 2 * t4;
                float v0 = (acc[mt][nt][half * 2 + 0] + b2[col] + tb) * bep[col];
                float v1 = (acc[mt][nt][half * 2 + 1] + b2[col + 1] + tb) * bep[col + 1];
                *(float2*)&g_bond[obase + col] = make_float2(v0, v1);
            }
        }
}

// ---------------- GIN GEMMs: 128x256 tile, pipelined ------------------------
#define GIN_SMEM ((2 * ASZ + 2 * BSZ) * 4)
template <int MODE>
__global__ void __launch_bounds__(256, 1)
gin_mma(const float* __restrict__ W, const float* __restrict__ bias, int reluOut) {
    extern __shared__ float sm[];
    float* As = sm;
    float* Bs = sm + 2 * ASZ;
    int tid = threadIdx.x, lane = tid & 31, warp = tid >> 5;
    int wy = warp >> 2, wx = warp & 3;
    int m0 = blockIdx.x * 128;
    int r = tid >> 1, kh = (tid & 1) * 8;
    int arow = m0 + r;
    bool valid = (arow < NN);
    const float* A1 = (MODE == 0) ? g_h : g_tmp;

    float areg[8], breg[16];
    auto loadA = [&](int k0) {
        if (valid) {
            const float* p = &A1[arow * H + k0 + kh];
            float4 v0 = *(const float4*)p, v1 = *(const float4*)(p + 4);
            areg[0] = v0.x; areg[1] = v0.y; areg[2] = v0.z; areg[3] = v0.w;
            areg[4] = v1.x; areg[5] = v1.y; areg[6] = v1.z; areg[7] = v1.w;
            if (MODE == 0) {
                const float* q = &g_aggr[arow * H + k0 + kh];
                float4 w0 = *(const float4*)q, w1 = *(const float4*)(q + 4);
                areg[0] += w0.x; areg[1] += w0.y; areg[2] += w0.z; areg[3] += w0.w;
                areg[4] += w1.x; areg[5] += w1.y; areg[6] += w1.z; areg[7] += w1.w;
            }
        } else {
#pragma unroll
            for (int i = 0; i < 8; i++) areg[i] = 0.f;
        }
    };

    loadA(0);
    load_w256(breg, W, H, 0, tid);
    store_a8(As, kh, r, areg);
    store_w256(Bs, breg, tid);
    __syncthreads();

    float acc[4][8][4] = {};
    for (int s = 0; s < 16; s++) {
        int cur = s & 1, nxt = cur ^ 1;
        if (s < 15) { loadA((s + 1) * 16); load_w256(breg, W, H, (s + 1) * 16, tid); }
        mma_k8w<PB>(acc, As + cur * ASZ, Bs + cur * BSZ, 0, wy, wx, lane);
        mma_k8w<PB>(acc, As + cur * ASZ, Bs + cur * BSZ, 8, wy, wx, lane);
        if (s < 15) {
            store_a8(As + nxt * ASZ, kh, r, areg);
            store_w256(Bs + nxt * BSZ, breg, tid);
            __syncthreads();
        }
    }

    int g = lane >> 2, t4 = lane & 3;
#pragma unroll
    for (int mt = 0; mt < 4; mt++)
#pragma unroll
        for (int half = 0; half < 2; half++) {
            int row = m0 + wy * 64 + mt * 16 + g + half * 8;
            if (row >= NN) continue;
#pragma unroll
            for (int nt = 0; nt < 8; nt++) {
                int col = wx * 64 + nt * 8 + 2 * t4;
                float v0 = acc[mt][nt][half * 2 + 0] + bias[col];
                float v1 = acc[mt][nt][half * 2 + 1] + bias[col + 1];
                if (reluOut) { v0 = fmaxf(v0, 0.f); v1 = fmaxf(v1, 0.f); }
                if (MODE == 0) {
                    *(float2*)&g_tmp[row * H + col] = make_float2(v0, v1);
                } else {
                    float2 rh = *(const float2*)&g_h[row * H + col];
                    *(float2*)&g_h[row * H + col] = make_float2(v0 + rh.x, v1 + rh.y);
                }
            }
        }
}

// ---------------- out1: K=512, 128x256 tile, pipelined ----------------------
#define OUT1_SMEM ((2 * ASZ + 2 * BSZ + 256) * 4)
__global__ void __launch_bounds__(256, 1)
out1(const int* __restrict__ src, const int* __restrict__ dst,
     const float* __restrict__ W1, const float* __restrict__ b1) {
    extern __shared__ float sm[];
    float* As = sm;
    float* Bs = sm + 2 * ASZ;
    int* srcS = (int*)(Bs + 2 * BSZ);   // 128
    int* dstS = srcS + 128;             // 128
    int tid = threadIdx.x, lane = tid & 31, warp = tid >> 5;
    int wy = warp >> 2, wx = warp & 3;
    int m0 = blockIdx.x * 128;

    if (tid < 128) {
        int e = m0 + tid;
        int s = 0, d = 0;
        if (e < EN) { s = src[e]; d = dst[e]; }
        srcS[tid] = s; dstS[tid] = d;
    }
    __syncthreads();

    int r = tid >> 1, kh = (tid & 1) * 8;
    int e = m0 + r;
    bool valid = (e < EN);
    float areg[8], breg[16];

    auto loadA = [&](int k0) {
        if (k0 < 256) {
            const float* hs = &g_h[srcS[r] * H + k0 + kh];
            const float* hd = &g_h[dstS[r] * H + k0 + kh];
            float4 a0 = *(const float4*)hs, a1 = *(const float4*)(hs + 4);
            float4 c0 = *(const float4*)hd, c1 = *(const float4*)(hd + 4);
            areg[0] = a0.x * c0.x; areg[1] = a0.y * c0.y;
            areg[2] = a0.z * c0.z; areg[3] = a0.w * c0.w;
            areg[4] = a1.x * c1.x; areg[5] = a1.y * c1.y;
            areg[6] = a1.z * c1.z; areg[7] = a1.w * c1.w;
        } else if (valid) {
            const float* bp = &g_bond[(size_t)e * H + (k0 - 256) + kh];
            float4 v0 = *(const float4*)bp, v1 = *(const float4*)(bp + 4);
            areg[0] = v0.x; areg[1] = v0.y; areg[2] = v0.z; areg[3] = v0.w;
            areg[4] = v1.x; areg[5] = v1.y; areg[6] = v1.z; areg[7] = v1.w;
        } else {
#pragma unroll
            for (int i = 0; i < 8; i++) areg[i] = 0.f;
        }
    };

    loadA(0);
    load_w256(breg, W1, H, 0, tid);
    store_a8(As, kh, r, areg);
    store_w256(Bs, breg, tid);
    __syncthreads();

    float acc[4][8][4] = {};
    for (int s = 0; s < 32; s++) {
        int cur = s & 1, nxt = cur ^ 1;
        if (s < 31) { loadA((s + 1) * 16); load_w256(breg, W1, H, (s + 1) * 16, tid); }
        mma_k8w<PB>(acc, As + cur * ASZ, Bs + cur * BSZ, 0, wy, wx, lane);
        mma_k8w<PB>(acc, As + cur * ASZ, Bs + cur * BSZ, 8, wy, wx, lane);
        if (s < 31) {
            store_a8(As + nxt * ASZ, kh, r, areg);
            store_w256(Bs + nxt * BSZ, breg, tid);
            __syncthreads();
        }
    }

    int g = lane >> 2, t4 = lane & 3;
#pragma unroll
    for (int mt = 0; mt < 4; mt++)
#pragma unroll
        for (int half = 0; half < 2; half++) {
            int row = m0 + wy * 64 + mt * 16 + g + half * 8;
            if (row >= EN) continue;
#pragma unroll
            for (int nt = 0; nt < 8; nt++) {
                int col = wx * 64 + nt * 8 + 2 * t4;
                float v0 = fmaxf(acc[mt][nt][half * 2 + 0] + b1[col], 0.f);
                float v1 = fmaxf(acc[mt][nt][half * 2 + 1] + b1[col + 1], 0.f);
                *(float2*)&g_h1[(size_t)row * H + col] = make_float2(v0, v1);
            }
        }
}

// ---------------- out23 fused: 128x128 tile, pipelined (static smem) --------
#define BSZ1 (16 * PB1)
__global__ void __launch_bounds__(128, 2)
out23(const float* __restrict__ W2, const float* __restrict__ b2,
      const float* __restrict__ W3, const float* __restrict__ b3,
      float* __restrict__ out) {
    __shared__ float As[2 * ASZ], Bs[2 * BSZ1];
    __shared__ float red[128 * 8];
    __shared__ float b2S[128], w3S[128];
    int tid = threadIdx.x, lane = tid & 31, warp = tid >> 5;
    int wy = warp >> 1, wx = warp & 1;
    int m0 = blockIdx.x * 128;

    b2S[tid] = b2[tid]; w3S[tid] = W3[tid];

    int e = m0 + tid;
    bool valid = (e < EN);
    float areg[16], breg[16];
    auto loadA = [&](int k0) {
        if (valid) {
            const float* p = &g_h1[(size_t)e * H + k0];
#pragma unroll
            for (int j = 0; j < 4; j++) {
                float4 v = *(const float4*)(p + 4 * j);
                areg[4 * j] = v.x; areg[4 * j + 1] = v.y;
                areg[4 * j + 2] = v.z; areg[4 * j + 3] = v.w;
            }
        } else {
#pragma unroll
            for (int i = 0; i < 16; i++) areg[i] = 0.f;
        }
    };

    loadA(0);
    load_w128(breg, W2, 128, 0, tid);
    store_a16(As, tid, areg);
    store_w128(Bs, breg, tid);
    __syncthreads();

    float acc[4][8][4] = {};
    for (int s = 0; s < 16; s++) {
        int cur = s & 1, nxt = cur ^ 1;
        if (s < 15) { loadA((s + 1) * 16); load_w128(breg, W2, 128, (s + 1) * 16, tid); }
        mma_k8w<PB1>(acc, As + cur * ASZ, Bs + cur * BSZ1, 0, wy, wx, lane);
        mma_k8w<PB1>(acc, As + cur * ASZ, Bs + cur * BSZ1, 8, wy, wx, lane);
        if (s < 15) {
            store_a16(As + nxt * ASZ, tid, areg);
            store_w128(Bs + nxt * BSZ1, breg, tid);
            __syncthreads();
        }
    }

    int g = lane >> 2, t4 = lane & 3;
#pragma unroll
    for (int mt = 0; mt < 4; mt++)
#pragma unroll
        for (int half = 0; half < 2; half++) {
            int rl = wy * 64 + mt * 16 + g + half * 8;
            float partial = 0.f;
#pragma unroll
            for (int nt = 0; nt < 8; nt++) {
                int col = wx * 64 + nt * 8 + 2 * t4;
                float h0 = fmaxf(acc[mt][nt][half * 2 + 0] + b2S[col], 0.f);
                float h1 = fmaxf(acc[mt][nt][half * 2 + 1] + b2S[col + 1], 0.f);
                partial += h0 * w3S[col] + h1 * w3S[col + 1];
            }
            red[rl * 8 + wx * 4 + t4] = partial;
        }
    __syncthreads();

    if (valid) {
        float s = 0.f;
#pragma unroll
        for (int i = 0; i < 8; i++) s += red[tid * 8 + i];
        out[e] = (s + b3[0]) * g_einv[e];
    }
}

// ---------------- launch ----------------------------------------------------
extern "C" void kernel_launch(void* const* d_in, const int* in_sizes, int n_in,
                              void* d_out, int out_size) {
    const int*   node_type = (const int*)d_in[0];
    const int*   edge_type = (const int*)d_in[1];
    const int*   edge_index = (const int*)d_in[2];
    const int*   batch = (const int*)d_in[3];
    const float* elen = (const float*)d_in[4];
    const float* t = (const float*)d_in[5];
    const float* atom_emb = (const float*)d_in[6];
    const float* bond_emb = (const float*)d_in[7];
    const float* in_W1 = (const float*)d_in[8];
    const float* in_b1 = (const float*)d_in[9];
    const float* in_W2 = (const float*)d_in[10];
    const float* in_b2 = (const float*)d_in[11];
    const float* fourier_W = (const float*)d_in[12];
    const float* temb_W = (const float*)d_in[13];
    const float* temb_b = (const float*)d_in[14];
    const float* d1W = (const float*)d_in[15];
    const float* d1b = (const float*)d_in[16];
    const float* gin_W1 = (const float*)d_in[17];
    const float* gin_b1 = (const float*)d_in[18];
    const float* gin_W2 = (const float*)d_in[19];
    const float* gin_b2 = (const float*)d_in[20];
    const float* out_W1 = (const float*)d_in[21];
    const float* out_b1 = (const float*)d_in[22];
    const float* out_W2 = (const float*)d_in[23];
    const float* out_b2 = (const float*)d_in[24];
    const float* out_W3 = (const float*)d_in[25];
    const float* out_b3 = (const float*)d_in[26];
    const int* src = edge_index;
    const int* dst = edge_index + EN;
    float* out = (float*)d_out;

    const int EB = (EN + 127) / 128;   // 2344
    const int NB = (NN + 127) / 128;   // 391

    static int attr_done = 0;
    if (!attr_done) {
        cudaFuncSetAttribute(edge_bond, cudaFuncAttributeMaxDynamicSharedMemorySize, EB_SMEM);
        cudaFuncSetAttribute(gin_mma<0>, cudaFuncAttributeMaxDynamicSharedMemorySize, GIN_SMEM);
        cudaFuncSetAttribute(gin_mma<1>, cudaFuncAttributeMaxDynamicSharedMemorySize, GIN_SMEM);
        cudaFuncSetAttribute(out1, cudaFuncAttributeMaxDynamicSharedMemorySize, OUT1_SMEM);
        attr_done = 1;
    }

    // launch order chosen so ncu (launch index 3) profiles edge_bond
    temb_fused<<<GN, 128>>>(t, fourier_W, temb_W, temb_b, d1W, d1b);      // 0
    hist<<<(EN + 255) / 256, 256>>>(dst);                                 // 1
    scan_kernel<<<1, 1024>>>();                                           // 2
    edge_bond<<<EB, 256, EB_SMEM>>>(elen, src, batch, edge_type,          // 3
                                    in_W1, in_b1, in_W2, in_b2, bond_emb);
    place<<<(EN + 255) / 256, 256>>>(src, dst);                           // 4
    init_h<<<(NN * 64 + 255) / 256, 256>>>(node_type, atom_emb);          // 5

    for (int c = 0; c < NCONV; c++) {
        gather<<<(NN + 7) / 8, 256>>>();
        gin_mma<0><<<NB, 256, GIN_SMEM>>>(gin_W1 + c * H * H, gin_b1 + c * H, 1);
        gin_mma<1><<<NB, 256, GIN_SMEM>>>(gin_W2 + c * H * H, gin_b2 + c * H,
                                          (c < NCONV - 1) ? 1 : 0);
    }

    out1<<<EB, 256, OUT1_SMEM>>>(src, dst, out_W1, out_b1);
    out23<<<EB, 128>>>(out_W2, out_b2, out_W3, out_b3, out);
}

// round 8
// speedup vs baseline: 2.5858x; 1.0564x over previous
#include <cuda_runtime.h>
#include <math.h>
#include <stdint.h>

#define EN 300000
#define NN 50000
#define GN 1024
#define H  256
#define NCONV 4
#define PA 136      // A smem row stride: 136 mod 32 == 8 -> conflict-free frag loads
#define PB 264      // B smem row stride (256-wide tiles): 264 mod 32 == 8
#define PB1 136     // B smem row stride (128-wide tiles)

// ---------------- scratch (device globals) ---------------------------------
static __device__ float g_bond[(size_t)EN * H];   // bond_attr [E,H] (edge order)
static __device__ float g_h1[(size_t)EN * H];     // out-MLP hidden1
static __device__ float g_h[NN * H];
static __device__ float g_aggr[NN * H];
static __device__ float g_tmp[NN * H];
static __device__ float g_temb[GN];
static __device__ float g_invstd[GN];
static __device__ float g_einv[EN];
// sort machinery
static __device__ int g_cnt[NN];      // zero-initialized; scan re-zeroes each call
static __device__ int g_rp[NN + 1];
static __device__ int g_woff[NN];
static __device__ int g_srcp[EN];     // sorted pos -> src node
static __device__ int g_eid[EN];      // sorted pos -> edge id

// ---------------- helpers ---------------------------------------------------
__device__ __forceinline__ float totf(float x) {
    uint32_t u; asm("cvt.rna.tf32.f32 %0, %1;" : "=r"(u) : "f"(x));
    return __uint_as_float(u);
}

// warp computes 64x64 via 32 mma m16n8k8 per k8 step
template <int BS>
__device__ __forceinline__ void mma_k8w(float acc[4][8][4],
                                        const float* As, const float* Bs,
                                        int kk, int wy, int wx, int lane) {
    int g = lane >> 2, t4 = lane & 3;
    float a[4][4];
#pragma unroll
    for (int mt = 0; mt < 4; mt++) {
        int rm = wy * 64 + mt * 16 + g;
        a[mt][0] = As[(kk + t4) * PA + rm];
        a[mt][1] = As[(kk + t4) * PA + rm + 8];
        a[mt][2] = As[(kk + t4 + 4) * PA + rm];
        a[mt][3] = As[(kk + t4 + 4) * PA + rm + 8];
    }
#pragma unroll
    for (int nt = 0; nt < 8; nt++) {
        int cn = wx * 64 + nt * 8 + g;
        float b0 = Bs[(kk + t4) * BS + cn];
        float b1 = Bs[(kk + t4 + 4) * BS + cn];
#pragma unroll
        for (int mt = 0; mt < 4; mt++) {
            asm volatile(
                "mma.sync.aligned.m16n8k8.row.col.f32.tf32.tf32.f32 "
                "{%0,%1,%2,%3}, {%4,%5,%6,%7}, {%8,%9}, {%0,%1,%2,%3};\n"
                : "+f"(acc[mt][nt][0]), "+f"(acc[mt][nt][1]),
                  "+f"(acc[mt][nt][2]), "+f"(acc[mt][nt][3])
                : "r"(__float_as_uint(a[mt][0])), "r"(__float_as_uint(a[mt][1])),
                  "r"(__float_as_uint(a[mt][2])), "r"(__float_as_uint(a[mt][3])),
                  "r"(__float_as_uint(b0)), "r"(__float_as_uint(b1)));
        }
    }
}

// B tile 16x256, 256 threads: thread owns COLUMN tid (conflict-free stores)
__device__ __forceinline__ void load_w256(float v[16], const float* __restrict__ W,
                                          int ldw, int k0, int tid) {
    const float* p = &W[(size_t)k0 * ldw + tid];
#pragma unroll
    for (int k = 0; k < 16; k++) v[k] = p[(size_t)k * ldw];
}
__device__ __forceinline__ void store_w256(float* Bs, const float v[16], int tid) {
#pragma unroll
    for (int k = 0; k < 16; k++) Bs[k * PB + tid] = totf(v[k]);
}
// B tile 16x128, 128 threads: thread owns column tid
__device__ __forceinline__ void load_w128(float v[16], const float* __restrict__ W,
                                          int ldw, int k0, int tid) {
    const float* p = &W[(size_t)k0 * ldw + tid];
#pragma unroll
    for (int k = 0; k < 16; k++) v[k] = p[(size_t)k * ldw];
}
__device__ __forceinline__ void store_w128(float* Bs, const float v[16], int tid) {
#pragma unroll
    for (int k = 0; k < 16; k++) Bs[k * PB1 + tid] = totf(v[k]);
}
// A: 256 threads, r = tid&127, kh = (tid>>7)*8 -> warp shares kh, stores conflict-free
__device__ __forceinline__ void store_a8(float* As, int kh, int r, const float v[8]) {
#pragma unroll
    for (int i = 0; i < 8; i++) As[(kh + i) * PA + r] = totf(v[i]);
}
// A: 128 threads, 16 k's of row tid (already conflict-free)
__device__ __forceinline__ void store_a16(float* As, int r, const float v[16]) {
#pragma unroll
    for (int k = 0; k < 16; k++) As[k * PA + r] = totf(v[k]);
}

// ---------------- temb (comb fused, coalesced) ------------------------------
__global__ void __launch_bounds__(128)
temb_fused(const float* __restrict__ t, const float* __restrict__ fw,
           const float* __restrict__ tW, const float* __restrict__ tb,
           const float* __restrict__ d1W, const float* __restrict__ d1b) {
    __shared__ float d1S[H], combS[H + 1], red[128];
    int tid = threadIdx.x, lane = tid & 31, warp = tid >> 5;
    d1S[tid] = d1W[tid]; d1S[tid + 128] = d1W[tid + 128];
    __syncthreads();
    for (int row = warp; row < H + 1; row += 4) {
        const float* p = (row < H) ? &tW[(size_t)row * H] : tb;
        float s = 0.f;
        for (int k = lane; k < H; k += 32) s += p[k] * d1S[k];
#pragma unroll
        for (int o = 16; o; o >>= 1) s += __shfl_down_sync(0xffffffffu, s, o);
        if (lane == 0) combS[row] = (row == H) ? s + d1b[0] : s;
    }
    __syncthreads();
    int g = blockIdx.x;
    float tt = t[g];
    float xp = tt * fw[tid] * 6.283185307179586f;
    red[tid] = sinf(xp) * combS[tid] + cosf(xp) * combS[128 + tid];
    __syncthreads();
    for (int s = 64; s > 0; s >>= 1) {
        if (tid < s) red[tid] += red[tid + s];
        __syncthreads();
    }
    if (tid == 0) {
        g_temb[g] = red[0] + combS[H];
        const float LS = 3.2188758248682006f;   // ln(25)
        float var = (expf(2.f * tt * LS) - 1.f) / (2.f * LS);
        g_invstd[g] = rsqrtf(var);
    }
}

// ---------------- sort machinery ---------------------------------------------
__global__ void __launch_bounds__(256) hist(const int* __restrict__ dst) {
    int e = blockIdx.x * blockDim.x + threadIdx.x;
    if (e < EN) atomicAdd(&g_cnt[dst[e]], 1);
}

__global__ void __launch_bounds__(1024) scan_kernel() {
    __shared__ int part[1024];
    const int CH = 49;
    int t = threadIdx.x;
    int beg = t * CH, end = min(beg + CH, NN);
    int s = 0;
    for (int i = beg; i < end; i++) s += g_cnt[i];
    part[t] = s;
    __syncthreads();
    for (int off = 1; off < 1024; off <<= 1) {
        int v = (t >= off) ? part[t - off] : 0;
        __syncthreads();
        part[t] += v;
        __syncthreads();
    }
    int run = (t == 0) ? 0 : part[t - 1];
    for (int i = beg; i < end; i++) {
        g_rp[i] = run; g_woff[i] = run; run += g_cnt[i];
        g_cnt[i] = 0;               // reset for next call (determinism)
    }
    if (t == 1023) g_rp[NN] = part[1023];
}

__global__ void __launch_bounds__(256) place(const int* __restrict__ src,
                                             const int* __restrict__ dst) {
    int e = blockIdx.x * blockDim.x + threadIdx.x;
    if (e >= EN) return;
    int p = atomicAdd(&g_woff[dst[e]], 1);
    g_srcp[p] = src[e];
    g_eid[p] = e;
}

__global__ void __launch_bounds__(256) init_h(const int* __restrict__ nt,
                                              const float* __restrict__ atom_emb) {
    int idx = blockIdx.x * blockDim.x + threadIdx.x;
    if (idx >= NN * 64) return;
    int n = idx >> 6, q = idx & 63;
    ((float4*)g_h)[idx] = ((const float4*)atom_emb)[nt[n] * 64 + q];
}

// ---------------- gather: aggr[n] = sum relu(h[src]+bond) -------------------
__global__ void __launch_bounds__(256) gather() {
    int warp = threadIdx.x >> 5, lane = threadIdx.x & 31;
    int n = blockIdx.x * 8 + warp;
    if (n >= NN) return;
    int q = lane * 8;
    float4 a0 = make_float4(0.f, 0.f, 0.f, 0.f), a1 = a0;
    int beg = g_rp[n], end = g_rp[n + 1];
    for (int p = beg; p < end; p++) {
        int s = g_srcp[p];
        int e = g_eid[p];
        const float4* hp = (const float4*)&g_h[s * H + q];
        const float4* bp = (const float4*)&g_bond[(size_t)e * H + q];
        float4 h0 = hp[0], h1v = hp[1], b0 = bp[0], b1v = bp[1];
        a0.x += fmaxf(h0.x + b0.x, 0.f);  a0.y += fmaxf(h0.y + b0.y, 0.f);
        a0.z += fmaxf(h0.z + b0.z, 0.f);  a0.w += fmaxf(h0.w + b0.w, 0.f);
        a1.x += fmaxf(h1v.x + b1v.x, 0.f); a1.y += fmaxf(h1v.y + b1v.y, 0.f);
        a1.z += fmaxf(h1v.z + b1v.z, 0.f); a1.w += fmaxf(h1v.w + b1v.w, 0.f);
    }
    float4* ap = (float4*)&g_aggr[n * H + q];
    ap[0] = a0; ap[1] = a1;
}

// ---------------- edge_bond: 128x256 tile, pipelined ------------------------
#define ASZ (16 * PA)
#define BSZ (16 * PB)
#define EB_SMEM ((2 * ASZ + 2 * BSZ + 128 + 128 + 128 + 2 * H) * 4)

__global__ void __launch_bounds__(256, 1)
edge_bond(const float* __restrict__ elen, const int* __restrict__ src,
          const int* __restrict__ batch, const int* __restrict__ etype,
          const float* __restrict__ W1, const float* __restrict__ b1,
          const float* __restrict__ W2, const float* __restrict__ b2,
          const float* __restrict__ bond_emb) {
    extern __shared__ float sm[];
    float* As = sm;                       // 2*ASZ
    float* Bs = sm + 2 * ASZ;             // 2*BSZ
    float* xS = Bs + 2 * BSZ;             // 128
    float* tS = xS + 128;                 // 128
    int*   eS = (int*)(tS + 128);         // 128
    float* w1S = (float*)(eS + 128);      // 256
    float* b1S = w1S + H;                 // 256

    int tid = threadIdx.x, lane = tid & 31, warp = tid >> 5;
    int wy = warp >> 2, wx = warp & 3;
    int m0 = blockIdx.x * 128;

    if (tid < 128) {
        int e = m0 + tid;
        float x = 0.f, tb = 0.f; int et = 0;
        if (e < EN) {
            x = elen[e];
            int gph = batch[src[e]];
            tb = g_temb[gph];
            g_einv[e] = g_invstd[gph];
            et = etype[e];
        }
        xS[tid] = x; tS[tid] = tb; eS[tid] = et;
    }
    w1S[tid] = W1[tid]; b1S[tid] = b1[tid];
    __syncthreads();

    int r = tid & 127, kh = (tid >> 7) * 8;
    float x = xS[r];
    float areg[8], breg[16];
    // prologue: step 0
#pragma unroll
    for (int i = 0; i < 8; i++)
        areg[i] = fmaxf(fmaf(x, w1S[kh + i], b1S[kh + i]), 0.f);
    load_w256(breg, W2, H, 0, tid);
    store_a8(As, kh, r, areg);
    store_w256(Bs, breg, tid);
    __syncthreads();

    float acc[4][8][4] = {};
    for (int s = 0; s < 16; s++) {
        int cur = s & 1, nxt = cur ^ 1;
        if (s < 15) {
            int k0 = (s + 1) * 16;
#pragma unroll
            for (int i = 0; i < 8; i++)
                areg[i] = fmaxf(fmaf(x, w1S[k0 + kh + i], b1S[k0 + kh + i]), 0.f);
            load_w256(breg, W2, H, k0, tid);
        }
        mma_k8w<PB>(acc, As + cur * ASZ, Bs + cur * BSZ, 0, wy, wx, lane);
        mma_k8w<PB>(acc, As + cur * ASZ, Bs + cur * BSZ, 8, wy, wx, lane);
        if (s < 15) {
            store_a8(As + nxt * ASZ, kh, r, areg);
            store_w256(Bs + nxt * BSZ, breg, tid);
            __syncthreads();
        }
    }

    int g = lane >> 2, t4 = lane & 3;
#pragma unroll
    for (int mt = 0; mt < 4; mt++)
#pragma unroll
        for (int half = 0; half < 2; half++) {
            int rl = wy * 64 + mt * 16 + g + half * 8;
            int row = m0 + rl;
            if (row >= EN) continue;
            float tb = tS[rl];
            const float* bep = &bond_emb[eS[rl] * H];
            size_t obase = (size_t)row * H;
#pragma unroll
            for (int nt = 0; nt < 8; nt++) {
                int col = wx * 64 + nt * 8 + 2 * t4;
                float v0 = (acc[mt][nt][half * 2 + 0] + b2[col] + tb) * bep[col];
                float v1 = (acc[mt][nt][half * 2 + 1] + b2[col + 1] + tb) * bep[col + 1];
                *(float2*)&g_bond[obase + col] = make_float2(v0, v1);
            }
        }
}

// ---------------- GIN GEMMs: 128x256 tile, pipelined ------------------------
#define GIN_SMEM ((2 * ASZ + 2 * BSZ) * 4)
template <int MODE>
__global__ void __launch_bounds__(256, 1)
gin_mma(const float* __restrict__ W, const float* __restrict__ bias, int reluOut) {
    extern __shared__ float sm[];
    float* As = sm;
    float* Bs = sm + 2 * ASZ;
    int tid = threadIdx.x, lane = tid & 31, warp = tid >> 5;
    int wy = warp >> 2, wx = warp & 3;
    int m0 = blockIdx.x * 128;
    int r = tid & 127, kh = (tid >> 7) * 8;
    int arow = m0 + r;
    bool valid = (arow < NN);
    const float* A1 = (MODE == 0) ? g_h : g_tmp;

    float areg[8], breg[16];
    auto loadA = [&](int k0) {
        if (valid) {
            const float* p = &A1[arow * H + k0 + kh];
            float4 v0 = *(const float4*)p, v1 = *(const float4*)(p + 4);
            areg[0] = v0.x; areg[1] = v0.y; areg[2] = v0.z; areg[3] = v0.w;
            areg[4] = v1.x; areg[5] = v1.y; areg[6] = v1.z; areg[7] = v1.w;
            if (MODE == 0) {
                const float* q = &g_aggr[arow * H + k0 + kh];
                float4 w0 = *(const float4*)q, w1 = *(const float4*)(q + 4);
                areg[0] += w0.x; areg[1] += w0.y; areg[2] += w0.z; areg[3] += w0.w;
                areg[4] += w1.x; areg[5] += w1.y; areg[6] += w1.z; areg[7] += w1.w;
            }
        } else {
#pragma unroll
            for (int i = 0; i < 8; i++) areg[i] = 0.f;
        }
    };

    loadA(0);
    load_w256(breg, W, H, 0, tid);
    store_a8(As, kh, r, areg);
    store_w256(Bs, breg, tid);
    __syncthreads();

    float acc[4][8][4] = {};
    for (int s = 0; s < 16; s++) {
        int cur = s & 1, nxt = cur ^ 1;
        if (s < 15) { loadA((s + 1) * 16); load_w256(breg, W, H, (s + 1) * 16, tid); }
        mma_k8w<PB>(acc, As + cur * ASZ, Bs + cur * BSZ, 0, wy, wx, lane);
        mma_k8w<PB>(acc, As + cur * ASZ, Bs + cur * BSZ, 8, wy, wx, lane);
        if (s < 15) {
            store_a8(As + nxt * ASZ, kh, r, areg);
            store_w256(Bs + nxt * BSZ, breg, tid);
            __syncthreads();
        }
    }

    int g = lane >> 2, t4 = lane & 3;
#pragma unroll
    for (int mt = 0; mt < 4; mt++)
#pragma unroll
        for (int half = 0; half < 2; half++) {
            int row = m0 + wy * 64 + mt * 16 + g + half * 8;
            if (row >= NN) continue;
#pragma unroll
            for (int nt = 0; nt < 8; nt++) {
                int col = wx * 64 + nt * 8 + 2 * t4;
                float v0 = acc[mt][nt][half * 2 + 0] + bias[col];
                float v1 = acc[mt][nt][half * 2 + 1] + bias[col + 1];
                if (reluOut) { v0 = fmaxf(v0, 0.f); v1 = fmaxf(v1, 0.f); }
                if (MODE == 0) {
                    *(float2*)&g_tmp[row * H + col] = make_float2(v0, v1);
                } else {
                    float2 rh = *(const float2*)&g_h[row * H + col];
                    *(float2*)&g_h[row * H + col] = make_float2(v0 + rh.x, v1 + rh.y);
                }
            }
        }
}

// ---------------- out1: K=512, 128x256 tile, pipelined ----------------------
#define OUT1_SMEM ((2 * ASZ + 2 * BSZ + 256) * 4)
__global__ void __launch_bounds__(256, 1)
out1(const int* __restrict__ src, const int* __restrict__ dst,
     const float* __restrict__ W1, const float* __restrict__ b1) {
    extern __shared__ float sm[];
    float* As = sm;
    float* Bs = sm + 2 * ASZ;
    int* srcS = (int*)(Bs + 2 * BSZ);   // 128
    int* dstS = srcS + 128;             // 128
    int tid = threadIdx.x, lane = tid & 31, warp = tid >> 5;
    int wy = warp >> 2, wx = warp & 3;
    int m0 = blockIdx.x * 128;

    if (tid < 128) {
        int e = m0 + tid;
        int s = 0, d = 0;
        if (e < EN) { s = src[e]; d = dst[e]; }
        srcS[tid] = s; dstS[tid] = d;
    }
    __syncthreads();

    int r = tid & 127, kh = (tid >> 7) * 8;
    int e = m0 + r;
    bool valid = (e < EN);
    float areg[8], breg[16];

    auto loadA = [&](int k0) {
        if (k0 < 256) {
            const float* hs = &g_h[srcS[r] * H + k0 + kh];
            const float* hd = &g_h[dstS[r] * H + k0 + kh];
            float4 a0 = *(const float4*)hs, a1 = *(const float4*)(hs + 4);
            float4 c0 = *(const float4*)hd, c1 = *(const float4*)(hd + 4);
            areg[0] = a0.x * c0.x; areg[1] = a0.y * c0.y;
            areg[2] = a0.z * c0.z; areg[3] = a0.w * c0.w;
            areg[4] = a1.x * c1.x; areg[5] = a1.y * c1.y;
            areg[6] = a1.z * c1.z; areg[7] = a1.w * c1.w;
        } else if (valid) {
            const float* bp = &g_bond[(size_t)e * H + (k0 - 256) + kh];
            float4 v0 = *(const float4*)bp, v1 = *(const float4*)(bp + 4);
            areg[0] = v0.x; areg[1] = v0.y; areg[2] = v0.z; areg[3] = v0.w;
            areg[4] = v1.x; areg[5] = v1.y; areg[6] = v1.z; areg[7] = v1.w;
        } else {
#pragma unroll
            for (int i = 0; i < 8; i++) areg[i] = 0.f;
        }
    };

    loadA(0);
    load_w256(breg, W1, H, 0, tid);
    store_a8(As, kh, r, areg);
    store_w256(Bs, breg, tid);
    __syncthreads();

    float acc[4][8][4] = {};
    for (int s = 0; s < 32; s++) {
        int cur = s & 1, nxt = cur ^ 1;
        if (s < 31) { loadA((s + 1) * 16); load_w256(breg, W1, H, (s + 1) * 16, tid); }
        mma_k8w<PB>(acc, As + cur * ASZ, Bs + cur * BSZ, 0, wy, wx, lane);
        mma_k8w<PB>(acc, As + cur * ASZ, Bs + cur * BSZ, 8, wy, wx, lane);
        if (s < 31) {
            store_a8(As + nxt * ASZ, kh, r, areg);
            store_w256(Bs + nxt * BSZ, breg, tid);
            __syncthreads();
        }
    }

    int g = lane >> 2, t4 = lane & 3;
#pragma unroll
    for (int mt = 0; mt < 4; mt++)
#pragma unroll
        for (int half = 0; half < 2; half++) {
            int row = m0 + wy * 64 + mt * 16 + g + half * 8;
            if (row >= EN) continue;
#pragma unroll
            for (int nt = 0; nt < 8; nt++) {
                int col = wx * 64 + nt * 8 + 2 * t4;
                float v0 = fmaxf(acc[mt][nt][half * 2 + 0] + b1[col], 0.f);
                float v1 = fmaxf(acc[mt][nt][half * 2 + 1] + b1[col + 1], 0.f);
                *(float2*)&g_h1[(size_t)row * H + col] = make_float2(v0, v1);
            }
        }
}

// ---------------- out23 fused: 128x128 tile, pipelined (static smem) --------
#define BSZ1 (16 * PB1)
__global__ void __launch_bounds__(128, 2)
out23(const float* __restrict__ W2, const float* __restrict__ b2,
      const float* __restrict__ W3, const float* __restrict__ b3,
      float* __restrict__ out) {
    __shared__ float As[2 * ASZ], Bs[2 * BSZ1];
    __shared__ float red[128 * 8];
    __shared__ float b2S[128], w3S[128];
    int tid = threadIdx.x, lane = tid & 31, warp = tid >> 5;
    int wy = warp >> 1, wx = warp & 1;
    int m0 = blockIdx.x * 128;

    b2S[tid] = b2[tid]; w3S[tid] = W3[tid];

    int e = m0 + tid;
    bool valid = (e < EN);
    float areg[16], breg[16];
    auto loadA = [&](int k0) {
        if (valid) {
            const float* p = &g_h1[(size_t)e * H + k0];
#pragma unroll
            for (int j = 0; j < 4; j++) {
                float4 v = *(const float4*)(p + 4 * j);
                areg[4 * j] = v.x; areg[4 * j + 1] = v.y;
                areg[4 * j + 2] = v.z; areg[4 * j + 3] = v.w;
            }
        } else {
#pragma unroll
            for (int i = 0; i < 16; i++) areg[i] = 0.f;
        }
    };

    loadA(0);
    load_w128(breg, W2, 128, 0, tid);
    store_a16(As, tid, areg);
    store_w128(Bs, breg, tid);
    __syncthreads();

    float acc[4][8][4] = {};
    for (int s = 0; s < 16; s++) {
        int cur = s & 1, nxt = cur ^ 1;
        if (s < 15) { loadA((s + 1) * 16); load_w128(breg, W2, 128, (s + 1) * 16, tid); }
        mma_k8w<PB1>(acc, As + cur * ASZ, Bs + cur * BSZ1, 0, wy, wx, lane);
        mma_k8w<PB1>(acc, As + cur * ASZ, Bs + cur * BSZ1, 8, wy, wx, lane);
        if (s < 15) {
            store_a16(As + nxt * ASZ, tid, areg);
            store_w128(Bs + nxt * BSZ1, breg, tid);
            __syncthreads();
        }
    }

    int g = lane >> 2, t4 = lane & 3;
#pragma unroll
    for (int mt = 0; mt < 4; mt++)
#pragma unroll
        for (int half = 0; half < 2; half++) {
            int rl = wy * 64 + mt * 16 + g + half * 8;
            float partial = 0.f;
#pragma unroll
            for (int nt = 0; nt < 8; nt++) {
                int col = wx * 64 + nt * 8 + 2 * t4;
                float h0 = fmaxf(acc[mt][nt][half * 2 + 0] + b2S[col], 0.f);
                float h1 = fmaxf(acc[mt][nt][half * 2 + 1] + b2S[col + 1], 0.f);
                partial += h0 * w3S[col] + h1 * w3S[col + 1];
            }
            red[rl * 8 + wx * 4 + t4] = partial;
        }
    __syncthreads();

    if (valid) {
        float s = 0.f;
#pragma unroll
        for (int i = 0; i < 8; i++) s += red[tid * 8 + i];
        out[e] = (s + b3[0]) * g_einv[e];
    }
}

// ---------------- launch ----------------------------------------------------
extern "C" void kernel_launch(void* const* d_in, const int* in_sizes, int n_in,
                              void* d_out, int out_size) {
    const int*   node_type = (const int*)d_in[0];
    const int*   edge_type = (const int*)d_in[1];
    const int*   edge_index = (const int*)d_in[2];
    const int*   batch = (const int*)d_in[3];
    const float* elen = (const float*)d_in[4];
    const float* t = (const float*)d_in[5];
    const float* atom_emb = (const float*)d_in[6];
    const float* bond_emb = (const float*)d_in[7];
    const float* in_W1 = (const float*)d_in[8];
    const float* in_b1 = (const float*)d_in[9];
    const float* in_W2 = (const float*)d_in[10];
    const float* in_b2 = (const float*)d_in[11];
    const float* fourier_W = (const float*)d_in[12];
    const float* temb_W = (const float*)d_in[13];
    const float* temb_b = (const float*)d_in[14];
    const float* d1W = (const float*)d_in[15];
    const float* d1b = (const float*)d_in[16];
    const float* gin_W1 = (const float*)d_in[17];
    const float* gin_b1 = (const float*)d_in[18];
    const float* gin_W2 = (const float*)d_in[19];
    const float* gin_b2 = (const float*)d_in[20];
    const float* out_W1 = (const float*)d_in[21];
    const float* out_b1 = (const float*)d_in[22];
    const float* out_W2 = (const float*)d_in[23];
    const float* out_b2 = (const float*)d_in[24];
    const float* out_W3 = (const float*)d_in[25];
    const float* out_b3 = (const float*)d_in[26];
    const int* src = edge_index;
    const int* dst = edge_index + EN;
    float* out = (float*)d_out;

    const int EB = (EN + 127) / 128;   // 2344
    const int NB = (NN + 127) / 128;   // 391

    static int attr_done = 0;
    if (!attr_done) {
        cudaFuncSetAttribute(edge_bond, cudaFuncAttributeMaxDynamicSharedMemorySize, EB_SMEM);
        cudaFuncSetAttribute(gin_mma<0>, cudaFuncAttributeMaxDynamicSharedMemorySize, GIN_SMEM);
        cudaFuncSetAttribute(gin_mma<1>, cudaFuncAttributeMaxDynamicSharedMemorySize, GIN_SMEM);
        cudaFuncSetAttribute(out1, cudaFuncAttributeMaxDynamicSharedMemorySize, OUT1_SMEM);
        attr_done = 1;
    }

    // launch order chosen so ncu (launch index 3) profiles edge_bond
    temb_fused<<<GN, 128>>>(t, fourier_W, temb_W, temb_b, d1W, d1b);      // 0
    hist<<<(EN + 255) / 256, 256>>>(dst);                                 // 1
    scan_kernel<<<1, 1024>>>();                                           // 2
    edge_bond<<<EB, 256, EB_SMEM>>>(elen, src, batch, edge_type,          // 3
                                    in_W1, in_b1, in_W2, in_b2, bond_emb);
    place<<<(EN + 255) / 256, 256>>>(src, dst);                           // 4
    init_h<<<(NN * 64 + 255) / 256, 256>>>(node_type, atom_emb);          // 5

    for (int c = 0; c < NCONV; c++) {
        gather<<<(NN + 7) / 8, 256>>>();
        gin_mma<0><<<NB, 256, GIN_SMEM>>>(gin_W1 + c * H * H, gin_b1 + c * H, 1);
        gin_mma<1><<<NB, 256, GIN_SMEM>>>(gin_W2 + c * H * H, gin_b2 + c * H,
                                          (c < NCONV - 1) ? 1 : 0);
    }

    out1<<<EB, 256, OUT1_SMEM>>>(src, dst, out_W1, out_b1);
    out23<<<EB, 128>>>(out_W2, out_b2, out_W3, out_b3, out);
}